// round 11
// baseline (speedup 1.0000x reference)
#include <cuda_runtime.h>
#include <cstdint>

#define TSEQ 2048
#define CH   2048
#define NH   16
#define HD   128

// Scratch (allocation-free rule: __device__ globals)
__device__ float g_q[TSEQ * CH];
__device__ float g_k[TSEQ * CH];
__device__ float g_v[TSEQ * CH];
__device__ float g_o[TSEQ * CH];
// tf32-rounded, K-group-permuted operands
__device__ float g_xp[TSEQ * CH];
__device__ float g_wqp[CH * CH];
__device__ float g_wkp[CH * CH];
__device__ float g_wvp[CH * CH];
__device__ float g_wop[CH * CH];
__device__ float g_op[TSEQ * CH];

// ===========================================================================
// helpers
// ===========================================================================
__device__ __forceinline__ uint32_t smem_to_u32(const void* p) {
    uint32_t a;
    asm("{ .reg .u64 t; cvta.to.shared.u64 t, %1; cvt.u32.u64 %0, t; }"
        : "=r"(a) : "l"(p));
    return a;
}

__device__ __forceinline__ void cp_async16(uint32_t dst, const void* src) {
    asm volatile("cp.async.cg.shared.global [%0], [%1], 16;"
                 :: "r"(dst), "l"(src) : "memory");
}
#define CP_COMMIT() asm volatile("cp.async.commit_group;" ::: "memory")
#define CP_WAIT0()  asm volatile("cp.async.wait_group 0;" ::: "memory")
#define CP_WAIT1()  asm volatile("cp.async.wait_group 1;" ::: "memory")

__device__ __forceinline__ uint32_t f2tf32(float x) {
    uint32_t r;
    asm("cvt.rna.tf32.f32 %0, %1;" : "=r"(r) : "f"(x));
    return r;
}
__device__ __forceinline__ float tf32r(float x) {
    return __uint_as_float(f2tf32(x));
}

// D = A @ B + C, m16n8k8 tf32, row.col
__device__ __forceinline__ void mma_tf32(float* d, const uint32_t* a,
                                         const uint32_t* b, const float* c) {
    asm volatile(
        "mma.sync.aligned.m16n8k8.row.col.f32.tf32.tf32.f32 "
        "{%0,%1,%2,%3}, {%4,%5,%6,%7}, {%8,%9}, {%10,%11,%12,%13};"
        : "=f"(d[0]), "=f"(d[1]), "=f"(d[2]), "=f"(d[3])
        : "r"(a[0]), "r"(a[1]), "r"(a[2]), "r"(a[3]),
          "r"(b[0]), "r"(b[1]),
          "f"(c[0]), "f"(c[1]), "f"(c[2]), "f"(c[3]));
}

// ===========================================================================
// round-to-tf32 + permute each 8-col K-group to [0,4,1,5,2,6,3,7]
// ===========================================================================
__global__ __launch_bounds__(256) void round_permute5(
    const float* __restrict__ s0, const float* __restrict__ s1,
    const float* __restrict__ s2, const float* __restrict__ s3,
    const float* __restrict__ s4,
    float* __restrict__ d0, float* __restrict__ d1, float* __restrict__ d2,
    float* __restrict__ d3, float* __restrict__ d4, int nmat) {
    const int i = blockIdx.x * blockDim.x + threadIdx.x;
    const int m = blockIdx.y;
    if (m >= nmat) return;
    const float* s = (m == 0) ? s0 : (m == 1) ? s1 : (m == 2) ? s2
                   : (m == 3) ? s3 : s4;
    float* d = (m == 0) ? d0 : (m == 1) ? d1 : (m == 2) ? d2
             : (m == 3) ? d3 : d4;
    float4 a = *(const float4*)(s + (size_t)i * 8);
    float4 b = *(const float4*)(s + (size_t)i * 8 + 4);
    float4 o0 = make_float4(tf32r(a.x), tf32r(b.x), tf32r(a.y), tf32r(b.y));
    float4 o1 = make_float4(tf32r(a.z), tf32r(b.z), tf32r(a.w), tf32r(b.w));
    *(float4*)(d + (size_t)i * 8)     = o0;
    *(float4*)(d + (size_t)i * 8 + 4) = o1;
}

// ===========================================================================
// C[M,N] = A[M,K] @ B[N,K]^T  (2048^3) via tf32 mma.sync (verified R7)
// roundz: blockIdx.z whose output is tf32-rounded at store (-1 = none)
// ===========================================================================
#define BK    16
#define LDS_P 24
#define P2    12
#define NTIL  (CH / BK)
#define GEMM_DSMEM (2 * 128 * LDS_P * 4 * 2)

__global__ __launch_bounds__(256, 2) void mma_gemm_p(
    const float* __restrict__ A,
    const float* __restrict__ B0, const float* __restrict__ B1,
    const float* __restrict__ B2,
    float* __restrict__ C0, float* __restrict__ C1, float* __restrict__ C2,
    int roundz) {
    extern __shared__ __align__(16) float gsm[];
    float* As = gsm;
    float* Bs = gsm + 2 * 128 * LDS_P;

    const float* B = (blockIdx.z == 0) ? B0 : (blockIdx.z == 1) ? B1 : B2;
    float*       C = (blockIdx.z == 0) ? C0 : (blockIdx.z == 1) ? C1 : C2;
    const bool rnd = ((int)blockIdx.z == roundz);

    const int tid  = threadIdx.x;
    const int lane = tid & 31;
    const int wid  = tid >> 5;
    const int wm   = (wid & 1) * 64;
    const int wn   = (wid >> 1) * 32;

    const int m0 = blockIdx.y * 128;
    const int n0 = blockIdx.x * 128;
    const float* Ab = A + (size_t)m0 * CH;
    const float* Bb = B + (size_t)n0 * CH;

    const uint32_t sA0 = smem_to_u32(As);
    const uint32_t sB0 = smem_to_u32(Bs);

    const int r0c = tid >> 2;
    const int c4  = (tid & 3) << 2;

    float acc[4][4][4];
#pragma unroll
    for (int mt = 0; mt < 4; mt++)
#pragma unroll
        for (int nt = 0; nt < 4; nt++)
#pragma unroll
            for (int e = 0; e < 4; e++) acc[mt][nt][e] = 0.f;

#pragma unroll
    for (int i = 0; i < 2; i++) {
        int row = r0c + i * 64;
        uint32_t off = (uint32_t)(row * LDS_P + c4) * 4u;
        cp_async16(sA0 + off, Ab + (size_t)row * CH + c4);
        cp_async16(sB0 + off, Bb + (size_t)row * CH + c4);
    }
    CP_COMMIT();

    for (int kt = 0; kt < NTIL; kt++) {
        CP_WAIT0();
        __syncthreads();

        if (kt + 1 < NTIL) {
            const int nbuf = (kt + 1) & 1;
            const int kc   = (kt + 1) * BK;
            const uint32_t sAd = sA0 + (uint32_t)(nbuf * 128 * LDS_P * 4);
            const uint32_t sBd = sB0 + (uint32_t)(nbuf * 128 * LDS_P * 4);
#pragma unroll
            for (int i = 0; i < 2; i++) {
                int row = r0c + i * 64;
                uint32_t off = (uint32_t)(row * LDS_P + c4) * 4u;
                cp_async16(sAd + off, Ab + (size_t)row * CH + kc + c4);
                cp_async16(sBd + off, Bb + (size_t)row * CH + kc + c4);
            }
            CP_COMMIT();
        }

        const int buf = kt & 1;
        const float2* Asb = (const float2*)(As + buf * 128 * LDS_P);
        const float2* Bsb = (const float2*)(Bs + buf * 128 * LDS_P);
#pragma unroll
        for (int ks = 0; ks < 2; ks++) {
            const int jq = ks * 4 + (lane & 3);
            uint32_t af[4][4], bf[4][2];
#pragma unroll
            for (int mt = 0; mt < 4; mt++) {
                int r = wm + mt * 16 + (lane >> 2);
                float2 f0 = Asb[r * P2 + jq];
                float2 f1 = Asb[(r + 8) * P2 + jq];
                af[mt][0] = __float_as_uint(f0.x);
                af[mt][1] = __float_as_uint(f1.x);
                af[mt][2] = __float_as_uint(f0.y);
                af[mt][3] = __float_as_uint(f1.y);
            }
#pragma unroll
            for (int nt = 0; nt < 4; nt++) {
                int cidx = wn + nt * 8 + (lane >> 2);
                float2 f = Bsb[cidx * P2 + jq];
                bf[nt][0] = __float_as_uint(f.x);
                bf[nt][1] = __float_as_uint(f.y);
            }
#pragma unroll
            for (int mt = 0; mt < 4; mt++)
#pragma unroll
                for (int nt = 0; nt < 4; nt++)
                    mma_tf32(acc[mt][nt], af[mt], bf[nt], acc[mt][nt]);
        }
        __syncthreads();
    }

#pragma unroll
    for (int mt = 0; mt < 4; mt++) {
        int r = m0 + wm + mt * 16 + (lane >> 2);
#pragma unroll
        for (int nt = 0; nt < 4; nt++) {
            int cidx = n0 + wn + nt * 8 + 2 * (lane & 3);
            float v0 = acc[mt][nt][0], v1 = acc[mt][nt][1];
            float v2 = acc[mt][nt][2], v3 = acc[mt][nt][3];
            if (rnd) { v0 = tf32r(v0); v1 = tf32r(v1);
                       v2 = tf32r(v2); v3 = tf32r(v3); }
            *(float2*)(C + (size_t)r * CH + cidx)       = make_float2(v0, v1);
            *(float2*)(C + (size_t)(r + 8) * CH + cidx) = make_float2(v2, v3);
        }
    }
}

// ---------------------------------------------------------------------------
// ReBased feature map; output tf32-rounded AND k-group-permuted
// [0,4,1,5,2,6,3,7] (so attention fragment fetches are LDS.64, no cvt).
// Numerically identical to rounding at fragment load (1-pass QK).
// ---------------------------------------------------------------------------
__global__ __launch_bounds__(256) void featmap(const float* __restrict__ gamma,
                                               const float* __restrict__ beta) {
    const int warp = threadIdx.x >> 5;
    const int lane = threadIdx.x & 31;
    const int row  = blockIdx.x * 8 + warp;
    float* base = (blockIdx.y == 0) ? g_q : g_k;
    const float scale = (blockIdx.y == 0) ? 0.08838834764831845f : 1.0f;
    const int t = row >> 4;
    const int h = row & 15;
    float* p = base + (size_t)t * CH + h * HD;

    float x[4];
    float s = 0.f, sq = 0.f;
#pragma unroll
    for (int r = 0; r < 4; r++) {
        int d = lane + 32 * r;
        float y = p[d] * gamma[d] + beta[d];
        x[r] = y;
        s  += y;
        sq += y * y;
    }
#pragma unroll
    for (int o = 16; o; o >>= 1) {
        s  += __shfl_xor_sync(0xFFFFFFFFu, s, o);   // also orders reads < writes
        sq += __shfl_xor_sync(0xFFFFFFFFu, sq, o);
    }
    const float mu  = s * (1.0f / HD);
    const float var = sq * (1.0f / HD) - mu * mu;
    const float rs  = rsqrtf(var + 1e-5f) * scale;
#pragma unroll
    for (int r = 0; r < 4; r++) {
        int d = lane + 32 * r;
        int pos = (d & ~7) | ((d & 3) << 1) | ((d >> 2) & 1);
        p[pos] = tf32r((x[r] - mu) * rs);
    }
}

// ===========================================================================
// Causal quadratic attention v4 — 256 thr / 8 warps, 2 CTAs/SM (113.9KB smem)
//   q-tile 64 rows, k-tile 32 rows. q/k pre-rounded+permuted (featmap),
//   v pre-rounded (GEMM epilogue). All fragment fetches LDS.64, zero cvt in
//   the mma loops. s2 tf32-rounded at store; z sums the same rounded values.
// QK warp tile 32x8 (2x4 grid); SV warp tile 32x32.
// smem: qs[64][132] | ks[2][32][132] | vt[2][128][36] | s2m[64][36] | z[64]
// ===========================================================================
#define ATTN_SMEM4 ((64*132 + 2*32*132 + 2*128*36 + 64*36 + 64) * 4)

__global__ __launch_bounds__(256, 2) void rebased_attn_mma() {
    extern __shared__ __align__(16) float asm_[];
    float* qs  = asm_;                      // [64][132]  (66 float2 pitch)
    float* ks  = qs + 64 * 132;             // [2][32][132]
    float* vt  = ks + 2 * 32 * 132;         // [2][128][36] (18 float2 pitch)
    float* s2m = vt + 2 * 128 * 36;         // [64][36]
    float* zsh = s2m + 64 * 36;             // [64]

    const int tid  = threadIdx.x;
    const int lane = tid & 31;
    const int wid  = tid >> 5;
    const int qt   = 31 - blockIdx.x;       // heavy tiles first
    const int h    = blockIdx.y;
    const int q0   = qt * 64;
    const int last = 2 * qt + 1;            // last k32-tile index

    const int wmQ = (wid & 1) * 32, wnQ = (wid >> 1) * 8;   // QK 32x8
    const int wnO = (wid >> 1) * 32;                        // SV 32x32 (rows = wmQ)

    const uint32_t qs_u = smem_to_u32(qs);
    const uint32_t ks_u = smem_to_u32(ks);

    // v prefetch slice: row vj (0..31), d-base per warp
    const int vj  = tid & 31;
    const int vdb = (tid >> 5) * 16;
    // permuted column for v transpose-store
    const int vw  = vj & 7;
    const int pj  = (vj & ~7) + ((vw < 4) ? vw * 2 : (vw - 4) * 2 + 1);

    // ---- prologue: cp.async q tile (64x128) + k tile 0 (32x128) ----
#pragma unroll
    for (int i = 0; i < 8; i++) {
        const int idx = tid + i * 256;
        const int r = idx >> 5, c = idx & 31;   // 32 chunks of 16B per row
        cp_async16(qs_u + (uint32_t)(r * 132 + c * 4) * 4u,
                   g_q + (size_t)(q0 + r) * CH + h * HD + c * 4);
    }
#pragma unroll
    for (int i = 0; i < 4; i++) {
        const int idx = tid + i * 256;
        const int r = idx >> 5, c = idx & 31;
        cp_async16(ks_u + (uint32_t)(r * 132 + c * 4) * 4u,
                   g_k + (size_t)r * CH + h * HD + c * 4);
    }
    CP_COMMIT();

    // prefetch v tile 0 into registers
    float4 vr[4];
    {
        const float* vs = g_v + (size_t)vj * CH + h * HD + vdb;
#pragma unroll
        for (int c = 0; c < 4; c++) vr[c] = *(const float4*)(vs + c * 4);
    }
    if (tid < 64) zsh[tid] = 0.f;

    float oacc[2][4][4];
#pragma unroll
    for (int mt = 0; mt < 2; mt++)
#pragma unroll
        for (int nt = 0; nt < 4; nt++)
#pragma unroll
            for (int e = 0; e < 4; e++) oacc[mt][nt][e] = 0.f;

    for (int kt = 0; kt <= last; kt++) {
        const int buf = kt & 1;

        // issue cp.async for k tile kt+1
        if (kt < last) {
            const uint32_t kd = ks_u + (uint32_t)(((kt + 1) & 1) * 32 * 132 * 4);
#pragma unroll
            for (int i = 0; i < 4; i++) {
                const int idx = tid + i * 256;
                const int r = idx >> 5, c = idx & 31;
                cp_async16(kd + (uint32_t)(r * 132 + c * 4) * 4u,
                           g_k + (size_t)((kt + 1) * 32 + r) * CH + h * HD + c * 4);
            }
            CP_COMMIT();
        }

        // store prefetched v (transposed, j-permuted; already tf32)
        {
            float* vtb = vt + buf * 128 * 36;
#pragma unroll
            for (int c = 0; c < 4; c++) {
                const int d0 = vdb + c * 4;
                vtb[(d0 + 0) * 36 + pj] = vr[c].x;
                vtb[(d0 + 1) * 36 + pj] = vr[c].y;
                vtb[(d0 + 2) * 36 + pj] = vr[c].z;
                vtb[(d0 + 3) * 36 + pj] = vr[c].w;
            }
        }
        // prefetch v tile kt+1
        if (kt < last) {
            const float* vs = g_v + (size_t)((kt + 1) * 32 + vj) * CH + h * HD + vdb;
#pragma unroll
            for (int c = 0; c < 4; c++) vr[c] = *(const float4*)(vs + c * 4);
        }

        if (kt < last) { CP_WAIT1(); } else { CP_WAIT0(); }
        __syncthreads();   // ks[buf]+vt[buf] ready; s2m free (prev SV done)

        // ---- S = q.k^T (1-pass tf32, pre-rounded operands, LDS.64 only) ----
        const float2* qf = (const float2*)qs;
        const float2* kf = (const float2*)ks + buf * 32 * 66;
        float sacc[2][4];
#pragma unroll
        for (int mt = 0; mt < 2; mt++)
#pragma unroll
            for (int e = 0; e < 4; e++) sacc[mt][e] = 0.f;

#pragma unroll 4
        for (int k8 = 0; k8 < 16; k8++) {
            const int fo = k8 * 4 + (lane & 3);
            float2 bfr = kf[(wnQ + (lane >> 2)) * 66 + fo];
            uint32_t bf[2] = {__float_as_uint(bfr.x), __float_as_uint(bfr.y)};
#pragma unroll
            for (int mt = 0; mt < 2; mt++) {
                const int r = wmQ + mt * 16 + (lane >> 2);
                float2 f0 = qf[r * 66 + fo];
                float2 f1 = qf[(r + 8) * 66 + fo];
                uint32_t af[4] = {__float_as_uint(f0.x), __float_as_uint(f1.x),
                                  __float_as_uint(f0.y), __float_as_uint(f1.y)};
                mma_tf32(sacc[mt], af, bf, sacc[mt]);
            }
        }

        // ---- square, mask, store tf32-rounded (permuted); z same values ----
        const bool msk = (kt >= 2 * qt);
        const int  off = kt * 32 - qt * 64;   // 0 or 32 when msk
        const int  j   = lane & 3;
        const int  p0  = (j < 2) ? 4 * j : 4 * j - 7;       // pos(2j)
        const int  p1  = (j < 2) ? 4 * j + 2 : 4 * j - 5;   // pos(2j+1)
#pragma unroll
        for (int mt = 0; mt < 2; mt++) {
            const int r0l = wmQ + mt * 16 + (lane >> 2);
            const int c0l = wnQ + 2 * j;
            float s0 = sacc[mt][0]; s0 *= s0;
            float s1 = sacc[mt][1]; s1 *= s1;
            float s2 = sacc[mt][2]; s2 *= s2;
            float s3 = sacc[mt][3]; s3 *= s3;
            if (msk) {
                if (c0l + off > r0l)         s0 = 0.f;
                if (c0l + 1 + off > r0l)     s1 = 0.f;
                if (c0l + off > r0l + 8)     s2 = 0.f;
                if (c0l + 1 + off > r0l + 8) s3 = 0.f;
            }
            s0 = tf32r(s0); s1 = tf32r(s1); s2 = tf32r(s2); s3 = tf32r(s3);
            s2m[r0l * 36 + wnQ + p0]       = s0;
            s2m[r0l * 36 + wnQ + p1]       = s1;
            s2m[(r0l + 8) * 36 + wnQ + p0] = s2;
            s2m[(r0l + 8) * 36 + wnQ + p1] = s3;
            atomicAdd(&zsh[r0l], s0 + s1);
            atomicAdd(&zsh[r0l + 8], s2 + s3);
        }
        __syncthreads();

        // ---- O += S2 @ V (1-pass tf32, LDS.64 only) ----
        const float2* sf = (const float2*)s2m;              // pitch 18
        const float2* vf = (const float2*)vt + buf * 128 * 18;
#pragma unroll
        for (int k8 = 0; k8 < 4; k8++) {
            const int fo = k8 * 4 + (lane & 3);
            uint32_t a[2][4];
#pragma unroll
            for (int mt = 0; mt < 2; mt++) {
                const int r = wmQ + mt * 16 + (lane >> 2);
                float2 f0 = sf[r * 18 + fo];
                float2 f1 = sf[(r + 8) * 18 + fo];
                a[mt][0] = __float_as_uint(f0.x);
                a[mt][1] = __float_as_uint(f1.x);
                a[mt][2] = __float_as_uint(f0.y);
                a[mt][3] = __float_as_uint(f1.y);
            }
#pragma unroll
            for (int nt = 0; nt < 4; nt++) {
                const int n = wnO + nt * 8 + (lane >> 2);
                float2 b2 = vf[n * 18 + fo];
                uint32_t b[2] = {__float_as_uint(b2.x), __float_as_uint(b2.y)};
#pragma unroll
                for (int mt = 0; mt < 2; mt++)
                    mma_tf32(oacc[mt][nt], a[mt], b, oacc[mt][nt]);
            }
        }
    }

    // ---- epilogue: divide by (z + eps), store ----
#pragma unroll
    for (int mt = 0; mt < 2; mt++) {
        const int rl = wmQ + mt * 16 + (lane >> 2);
        const float inv0 = 1.0f / (zsh[rl] + 1e-5f);
        const float inv1 = 1.0f / (zsh[rl + 8] + 1e-5f);
        float* o0 = g_o + (size_t)(q0 + rl) * CH + h * HD;
        float* o1 = g_o + (size_t)(q0 + rl + 8) * CH + h * HD;
#pragma unroll
        for (int nt = 0; nt < 4; nt++) {
            const int cl = wnO + nt * 8 + 2 * (lane & 3);
            *(float2*)(o0 + cl) = make_float2(oacc[mt][nt][0] * inv0,
                                              oacc[mt][nt][1] * inv0);
            *(float2*)(o1 + cl) = make_float2(oacc[mt][nt][2] * inv1,
                                              oacc[mt][nt][3] * inv1);
        }
    }
}

// ---------------------------------------------------------------------------
extern "C" void kernel_launch(void* const* d_in, const int* in_sizes, int n_in,
                              void* d_out, int out_size) {
    const float* X     = (const float*)d_in[0];
    const float* Wq    = (const float*)d_in[1];
    const float* Wk    = (const float*)d_in[2];
    const float* Wv    = (const float*)d_in[3];
    const float* Wo    = (const float*)d_in[4];
    const float* gamma = (const float*)d_in[5];
    const float* beta  = (const float*)d_in[6];
    float* out = (float*)d_out;

    float *q, *k, *v, *o, *xp, *wqp, *wkp, *wvp, *wop, *op;
    cudaGetSymbolAddress((void**)&q, g_q);
    cudaGetSymbolAddress((void**)&k, g_k);
    cudaGetSymbolAddress((void**)&v, g_v);
    cudaGetSymbolAddress((void**)&o, g_o);
    cudaGetSymbolAddress((void**)&xp, g_xp);
    cudaGetSymbolAddress((void**)&wqp, g_wqp);
    cudaGetSymbolAddress((void**)&wkp, g_wkp);
    cudaGetSymbolAddress((void**)&wvp, g_wvp);
    cudaGetSymbolAddress((void**)&wop, g_wop);
    cudaGetSymbolAddress((void**)&op, g_op);

    cudaFuncSetAttribute(rebased_attn_mma,
                         cudaFuncAttributeMaxDynamicSharedMemorySize, ATTN_SMEM4);
    cudaFuncSetAttribute(rebased_attn_mma,
                         cudaFuncAttributePreferredSharedMemoryCarveout, 100);
    cudaFuncSetAttribute(mma_gemm_p,
                         cudaFuncAttributeMaxDynamicSharedMemorySize, GEMM_DSMEM);

    dim3 b256(256);
    const int NGRP = TSEQ * CH / 8;

    // pre-round + K-group permute: X, Wq, Wk, Wv, Wo
    round_permute5<<<dim3(NGRP / 256, 5), b256>>>(
        X, Wq, Wk, Wv, Wo, xp, wqp, wkp, wvp, wop, 5);

    // fused Q/K/V projections (v output tf32-rounded in epilogue)
    mma_gemm_p<<<dim3(16, 16, 3), b256, GEMM_DSMEM>>>(
        xp, wqp, wkp, wvp, q, k, v, 2);

    // feature map (q scaled by D^-0.5, k unscaled; rounded + permuted out)
    featmap<<<dim3(TSEQ * NH / 8, 2), b256>>>(gamma, beta);

    // causal quadratic attention (2 CTAs/SM, LDS.64-only fragment fetches)
    rebased_attn_mma<<<dim3(TSEQ / 64, NH), b256, ATTN_SMEM4>>>();

    // round+permute attention output, then O projection
    round_permute5<<<dim3(NGRP / 256, 1), b256>>>(
        o, o, o, o, o, op, op, op, op, op, 1);
    mma_gemm_p<<<dim3(16, 16, 1), b256, GEMM_DSMEM>>>(
        op, wop, wop, wop, out, out, out, -1);
}

// round 12
// speedup vs baseline: 1.1919x; 1.1919x over previous
#include <cuda_runtime.h>
#include <cstdint>

#define TSEQ 2048
#define CH   2048
#define NH   16
#define HD   128

// Scratch (allocation-free rule: __device__ globals)
__device__ float g_q[TSEQ * CH];
__device__ float g_k[TSEQ * CH];
__device__ float g_v[TSEQ * CH];
__device__ float g_o[TSEQ * CH];
// tf32-rounded, K-group-permuted operands
__device__ float g_xp[TSEQ * CH];
__device__ float g_wqp[CH * CH];
__device__ float g_wkp[CH * CH];
__device__ float g_wvp[CH * CH];
__device__ float g_wop[CH * CH];
__device__ float g_op[TSEQ * CH];

// ===========================================================================
// helpers
// ===========================================================================
__device__ __forceinline__ uint32_t smem_to_u32(const void* p) {
    uint32_t a;
    asm("{ .reg .u64 t; cvta.to.shared.u64 t, %1; cvt.u32.u64 %0, t; }"
        : "=r"(a) : "l"(p));
    return a;
}

__device__ __forceinline__ void cp_async16(uint32_t dst, const void* src) {
    asm volatile("cp.async.cg.shared.global [%0], [%1], 16;"
                 :: "r"(dst), "l"(src) : "memory");
}
#define CP_COMMIT() asm volatile("cp.async.commit_group;" ::: "memory")
#define CP_WAIT0()  asm volatile("cp.async.wait_group 0;" ::: "memory")
#define CP_WAIT1()  asm volatile("cp.async.wait_group 1;" ::: "memory")

__device__ __forceinline__ uint32_t f2tf32(float x) {
    uint32_t r;
    asm("cvt.rna.tf32.f32 %0, %1;" : "=r"(r) : "f"(x));
    return r;
}
__device__ __forceinline__ float tf32r(float x) {
    return __uint_as_float(f2tf32(x));
}

// D = A @ B + C, m16n8k8 tf32, row.col
__device__ __forceinline__ void mma_tf32(float* d, const uint32_t* a,
                                         const uint32_t* b, const float* c) {
    asm volatile(
        "mma.sync.aligned.m16n8k8.row.col.f32.tf32.tf32.f32 "
        "{%0,%1,%2,%3}, {%4,%5,%6,%7}, {%8,%9}, {%10,%11,%12,%13};"
        : "=f"(d[0]), "=f"(d[1]), "=f"(d[2]), "=f"(d[3])
        : "r"(a[0]), "r"(a[1]), "r"(a[2]), "r"(a[3]),
          "r"(b[0]), "r"(b[1]),
          "f"(c[0]), "f"(c[1]), "f"(c[2]), "f"(c[3]));
}

// ===========================================================================
// round-to-tf32 + permute each 8-col K-group to [0,4,1,5,2,6,3,7]
// ===========================================================================
__global__ __launch_bounds__(256) void round_permute5(
    const float* __restrict__ s0, const float* __restrict__ s1,
    const float* __restrict__ s2, const float* __restrict__ s3,
    const float* __restrict__ s4,
    float* __restrict__ d0, float* __restrict__ d1, float* __restrict__ d2,
    float* __restrict__ d3, float* __restrict__ d4, int nmat) {
    const int i = blockIdx.x * blockDim.x + threadIdx.x;
    const int m = blockIdx.y;
    if (m >= nmat) return;
    const float* s = (m == 0) ? s0 : (m == 1) ? s1 : (m == 2) ? s2
                   : (m == 3) ? s3 : s4;
    float* d = (m == 0) ? d0 : (m == 1) ? d1 : (m == 2) ? d2
             : (m == 3) ? d3 : d4;
    float4 a = *(const float4*)(s + (size_t)i * 8);
    float4 b = *(const float4*)(s + (size_t)i * 8 + 4);
    float4 o0 = make_float4(tf32r(a.x), tf32r(b.x), tf32r(a.y), tf32r(b.y));
    float4 o1 = make_float4(tf32r(a.z), tf32r(b.z), tf32r(a.w), tf32r(b.w));
    *(float4*)(d + (size_t)i * 8)     = o0;
    *(float4*)(d + (size_t)i * 8 + 4) = o1;
}

// ===========================================================================
// C[M,N] = A[M,K] @ B[N,K]^T  (2048^3) via tf32 mma.sync (verified R7)
// roundz: blockIdx.z whose output is tf32-rounded at store (-1 = none)
// ===========================================================================
#define BK    16
#define LDS_P 24
#define P2    12
#define NTIL  (CH / BK)
#define GEMM_DSMEM (2 * 128 * LDS_P * 4 * 2)

__global__ __launch_bounds__(256, 2) void mma_gemm_p(
    const float* __restrict__ A,
    const float* __restrict__ B0, const float* __restrict__ B1,
    const float* __restrict__ B2,
    float* __restrict__ C0, float* __restrict__ C1, float* __restrict__ C2,
    int roundz) {
    extern __shared__ __align__(16) float gsm[];
    float* As = gsm;
    float* Bs = gsm + 2 * 128 * LDS_P;

    const float* B = (blockIdx.z == 0) ? B0 : (blockIdx.z == 1) ? B1 : B2;
    float*       C = (blockIdx.z == 0) ? C0 : (blockIdx.z == 1) ? C1 : C2;
    const bool rnd = ((int)blockIdx.z == roundz);

    const int tid  = threadIdx.x;
    const int lane = tid & 31;
    const int wid  = tid >> 5;
    const int wm   = (wid & 1) * 64;
    const int wn   = (wid >> 1) * 32;

    const int m0 = blockIdx.y * 128;
    const int n0 = blockIdx.x * 128;
    const float* Ab = A + (size_t)m0 * CH;
    const float* Bb = B + (size_t)n0 * CH;

    const uint32_t sA0 = smem_to_u32(As);
    const uint32_t sB0 = smem_to_u32(Bs);

    const int r0c = tid >> 2;
    const int c4  = (tid & 3) << 2;

    float acc[4][4][4];
#pragma unroll
    for (int mt = 0; mt < 4; mt++)
#pragma unroll
        for (int nt = 0; nt < 4; nt++)
#pragma unroll
            for (int e = 0; e < 4; e++) acc[mt][nt][e] = 0.f;

#pragma unroll
    for (int i = 0; i < 2; i++) {
        int row = r0c + i * 64;
        uint32_t off = (uint32_t)(row * LDS_P + c4) * 4u;
        cp_async16(sA0 + off, Ab + (size_t)row * CH + c4);
        cp_async16(sB0 + off, Bb + (size_t)row * CH + c4);
    }
    CP_COMMIT();

    for (int kt = 0; kt < NTIL; kt++) {
        CP_WAIT0();
        __syncthreads();

        if (kt + 1 < NTIL) {
            const int nbuf = (kt + 1) & 1;
            const int kc   = (kt + 1) * BK;
            const uint32_t sAd = sA0 + (uint32_t)(nbuf * 128 * LDS_P * 4);
            const uint32_t sBd = sB0 + (uint32_t)(nbuf * 128 * LDS_P * 4);
#pragma unroll
            for (int i = 0; i < 2; i++) {
                int row = r0c + i * 64;
                uint32_t off = (uint32_t)(row * LDS_P + c4) * 4u;
                cp_async16(sAd + off, Ab + (size_t)row * CH + kc + c4);
                cp_async16(sBd + off, Bb + (size_t)row * CH + kc + c4);
            }
            CP_COMMIT();
        }

        const int buf = kt & 1;
        const float2* Asb = (const float2*)(As + buf * 128 * LDS_P);
        const float2* Bsb = (const float2*)(Bs + buf * 128 * LDS_P);
#pragma unroll
        for (int ks = 0; ks < 2; ks++) {
            const int jq = ks * 4 + (lane & 3);
            uint32_t af[4][4], bf[4][2];
#pragma unroll
            for (int mt = 0; mt < 4; mt++) {
                int r = wm + mt * 16 + (lane >> 2);
                float2 f0 = Asb[r * P2 + jq];
                float2 f1 = Asb[(r + 8) * P2 + jq];
                af[mt][0] = __float_as_uint(f0.x);
                af[mt][1] = __float_as_uint(f1.x);
                af[mt][2] = __float_as_uint(f0.y);
                af[mt][3] = __float_as_uint(f1.y);
            }
#pragma unroll
            for (int nt = 0; nt < 4; nt++) {
                int cidx = wn + nt * 8 + (lane >> 2);
                float2 f = Bsb[cidx * P2 + jq];
                bf[nt][0] = __float_as_uint(f.x);
                bf[nt][1] = __float_as_uint(f.y);
            }
#pragma unroll
            for (int mt = 0; mt < 4; mt++)
#pragma unroll
                for (int nt = 0; nt < 4; nt++)
                    mma_tf32(acc[mt][nt], af[mt], bf[nt], acc[mt][nt]);
        }
        __syncthreads();
    }

#pragma unroll
    for (int mt = 0; mt < 4; mt++) {
        int r = m0 + wm + mt * 16 + (lane >> 2);
#pragma unroll
        for (int nt = 0; nt < 4; nt++) {
            int cidx = n0 + wn + nt * 8 + 2 * (lane & 3);
            float v0 = acc[mt][nt][0], v1 = acc[mt][nt][1];
            float v2 = acc[mt][nt][2], v3 = acc[mt][nt][3];
            if (rnd) { v0 = tf32r(v0); v1 = tf32r(v1);
                       v2 = tf32r(v2); v3 = tf32r(v3); }
            *(float2*)(C + (size_t)r * CH + cidx)       = make_float2(v0, v1);
            *(float2*)(C + (size_t)(r + 8) * CH + cidx) = make_float2(v2, v3);
        }
    }
}

// ---------------------------------------------------------------------------
// ReBased feature map; output tf32-rounded AND k-group-permuted
// [0,4,1,5,2,6,3,7] (validated R11: rel_err identical to R9).
// ---------------------------------------------------------------------------
__global__ __launch_bounds__(256) void featmap(const float* __restrict__ gamma,
                                               const float* __restrict__ beta) {
    const int warp = threadIdx.x >> 5;
    const int lane = threadIdx.x & 31;
    const int row  = blockIdx.x * 8 + warp;
    float* base = (blockIdx.y == 0) ? g_q : g_k;
    const float scale = (blockIdx.y == 0) ? 0.08838834764831845f : 1.0f;
    const int t = row >> 4;
    const int h = row & 15;
    float* p = base + (size_t)t * CH + h * HD;

    float x[4];
    float s = 0.f, sq = 0.f;
#pragma unroll
    for (int r = 0; r < 4; r++) {
        int d = lane + 32 * r;
        float y = p[d] * gamma[d] + beta[d];
        x[r] = y;
        s  += y;
        sq += y * y;
    }
#pragma unroll
    for (int o = 16; o; o >>= 1) {
        s  += __shfl_xor_sync(0xFFFFFFFFu, s, o);   // also orders reads < writes
        sq += __shfl_xor_sync(0xFFFFFFFFu, sq, o);
    }
    const float mu  = s * (1.0f / HD);
    const float var = sq * (1.0f / HD) - mu * mu;
    const float rs  = rsqrtf(var + 1e-5f) * scale;
#pragma unroll
    for (int r = 0; r < 4; r++) {
        int d = lane + 32 * r;
        int pos = (d & ~7) | ((d & 3) << 1) | ((d >> 2) & 1);
        p[pos] = tf32r((x[r] - mu) * rs);
    }
}

// ===========================================================================
// Causal quadratic attention v5 — R9 frame (64-row k-tiles, 8 warps,
// 1 CTA/SM, 2 barriers/tile) + validated zero-cvt permuted layouts with
// conflict-free float2 pitches (68 f2 for q/k, 36 f2 for vt/s2m; ≡4 mod 16).
// QK warp tile 32x16 (2x4), SV 32x32. cp.async double-buffered k,
// register-prefetched v (rounded upstream), s2 tf32-rounded at store.
// smem: qs[64][136] | ks[2][64][136] | vt[2][128][72] | s2m[64][72] | z[64]
// = 196,864 B
// ===========================================================================
#define QP 136   // q/k float pitch  (68 float2)
#define VP 72    // vt/s2m float pitch (36 float2)
#define ATTN_SMEM5 ((64*QP + 2*64*QP + 2*128*VP + 64*VP + 64) * 4)

__global__ __launch_bounds__(256, 1) void rebased_attn_mma() {
    extern __shared__ __align__(16) float asm_[];
    float* qs  = asm_;                      // [64][QP]
    float* ks  = qs + 64 * QP;              // [2][64][QP]
    float* vt  = ks + 2 * 64 * QP;          // [2][128][VP]
    float* s2m = vt + 2 * 128 * VP;         // [64][VP]
    float* zsh = s2m + 64 * VP;             // [64]

    const int tid  = threadIdx.x;
    const int lane = tid & 31;
    const int wid  = tid >> 5;
    const int qt   = 31 - blockIdx.x;       // heavy tiles first
    const int h    = blockIdx.y;
    const int q0   = qt * 64;

    const int wmQ = (wid & 1) * 32, wnQ = (wid >> 1) * 16;  // QK 32x16
    const int wmO = (wid & 1) * 32, wnO = (wid >> 1) * 32;  // SV 32x32

    const uint32_t qs_u = smem_to_u32(qs);
    const uint32_t ks_u = smem_to_u32(ks);

    // v prefetch slice (R9 mapping): 32 floats per thread
    const int vj  = tid & 63;
    const int vdb = (tid >> 6) * 4;
    // permuted column for v transpose-store (bijection within 8-groups)
    const int vw  = vj & 7;
    const int pj  = (vj & ~7) + ((vw < 4) ? vw * 2 : (vw - 4) * 2 + 1);

    // ---- prologue: cp.async q tile (64x128) + k tile 0 (64x128) ----
#pragma unroll
    for (int i = 0; i < 8; i++) {
        const int idx = tid + i * 256;
        const int r = idx >> 5, c = idx & 31;   // 32 x 16B chunks per row
        cp_async16(qs_u + (uint32_t)(r * QP + c * 4) * 4u,
                   g_q + (size_t)(q0 + r) * CH + h * HD + c * 4);
        cp_async16(ks_u + (uint32_t)(r * QP + c * 4) * 4u,
                   g_k + (size_t)r * CH + h * HD + c * 4);
    }
    CP_COMMIT();

    // prefetch v tile 0 into registers (already tf32-rounded upstream)
    float4 vr[8];
    {
        const float* vs = g_v + (size_t)vj * CH + h * HD;
#pragma unroll
        for (int c = 0; c < 8; c++) vr[c] = *(const float4*)(vs + vdb + c * 16);
    }
    if (tid < 64) zsh[tid] = 0.f;

    float oacc[2][4][4];
#pragma unroll
    for (int mt = 0; mt < 2; mt++)
#pragma unroll
        for (int nt = 0; nt < 4; nt++)
#pragma unroll
            for (int e = 0; e < 4; e++) oacc[mt][nt][e] = 0.f;

    for (int kt = 0; kt <= qt; kt++) {
        const int buf = kt & 1;

        // issue cp.async for k tile kt+1 (other buffer)
        if (kt < qt) {
            const int kn = (kt + 1) * 64;
            const uint32_t kd = ks_u + (uint32_t)(((kt + 1) & 1) * 64 * QP * 4);
#pragma unroll
            for (int i = 0; i < 8; i++) {
                const int idx = tid + i * 256;
                const int r = idx >> 5, c = idx & 31;
                cp_async16(kd + (uint32_t)(r * QP + c * 4) * 4u,
                           g_k + (size_t)(kn + r) * CH + h * HD + c * 4);
            }
            CP_COMMIT();
        }

        // store prefetched v (transposed, j-permuted; values already tf32)
        {
            float* vtb = vt + buf * 128 * VP;
#pragma unroll
            for (int c = 0; c < 8; c++) {
                const int d0 = vdb + c * 16;
                vtb[(d0 + 0) * VP + pj] = vr[c].x;
                vtb[(d0 + 1) * VP + pj] = vr[c].y;
                vtb[(d0 + 2) * VP + pj] = vr[c].z;
                vtb[(d0 + 3) * VP + pj] = vr[c].w;
            }
        }
        // prefetch v tile kt+1
        if (kt < qt) {
            const float* vs = g_v + (size_t)((kt + 1) * 64 + vj) * CH + h * HD;
#pragma unroll
            for (int c = 0; c < 8; c++)
                vr[c] = *(const float4*)(vs + vdb + c * 16);
        }

        if (kt < qt) { CP_WAIT1(); } else { CP_WAIT0(); }
        __syncthreads();   // ks[buf] + vt[buf] ready; s2m free

        // ---- S = q.k^T (1-pass tf32; pre-rounded+permuted, LDS.64 only) ----
        const float2* qf = (const float2*)qs;                 // pitch 68
        const float2* kf = (const float2*)ks + buf * 64 * (QP / 2);
        float sacc[2][2][4];
#pragma unroll
        for (int mt = 0; mt < 2; mt++)
#pragma unroll
            for (int nt = 0; nt < 2; nt++)
#pragma unroll
                for (int e = 0; e < 4; e++) sacc[mt][nt][e] = 0.f;

#pragma unroll 4
        for (int k8 = 0; k8 < 16; k8++) {
            const int fo = k8 * 4 + (lane & 3);
            uint32_t af[2][4], bf[2][2];
#pragma unroll
            for (int mt = 0; mt < 2; mt++) {
                const int r = wmQ + mt * 16 + (lane >> 2);
                float2 f0 = qf[r * (QP / 2) + fo];
                float2 f1 = qf[(r + 8) * (QP / 2) + fo];
                af[mt][0] = __float_as_uint(f0.x);
                af[mt][1] = __float_as_uint(f1.x);
                af[mt][2] = __float_as_uint(f0.y);
                af[mt][3] = __float_as_uint(f1.y);
            }
#pragma unroll
            for (int nt = 0; nt < 2; nt++) {
                const int n = wnQ + nt * 8 + (lane >> 2);
                float2 f = kf[n * (QP / 2) + fo];
                bf[nt][0] = __float_as_uint(f.x);
                bf[nt][1] = __float_as_uint(f.y);
            }
#pragma unroll
            for (int mt = 0; mt < 2; mt++)
#pragma unroll
                for (int nt = 0; nt < 2; nt++)
                    mma_tf32(sacc[mt][nt], af[mt], bf[nt], sacc[mt][nt]);
        }

        // ---- square, mask, store tf32-rounded (permuted); z same values ----
        const bool diag = (kt == qt);
        const int  j   = lane & 3;
        const int  p0  = (j < 2) ? 4 * j : 4 * j - 7;       // pos(2j)
        const int  p1  = (j < 2) ? 4 * j + 2 : 4 * j - 5;   // pos(2j+1)
#pragma unroll
        for (int mt = 0; mt < 2; mt++) {
            const int r0l = wmQ + mt * 16 + (lane >> 2);
            float zp0 = 0.f, zp1 = 0.f;
#pragma unroll
            for (int nt = 0; nt < 2; nt++) {
                const int cb  = wnQ + nt * 8;
                const int c0l = cb + 2 * j;
                float s0 = sacc[mt][nt][0]; s0 *= s0;
                float s1 = sacc[mt][nt][1]; s1 *= s1;
                float s2 = sacc[mt][nt][2]; s2 *= s2;
                float s3 = sacc[mt][nt][3]; s3 *= s3;
                if (diag) {
                    if (c0l > r0l)         s0 = 0.f;
                    if (c0l + 1 > r0l)     s1 = 0.f;
                    if (c0l > r0l + 8)     s2 = 0.f;
                    if (c0l + 1 > r0l + 8) s3 = 0.f;
                }
                s0 = tf32r(s0); s1 = tf32r(s1); s2 = tf32r(s2); s3 = tf32r(s3);
                s2m[r0l * VP + cb + p0]       = s0;
                s2m[r0l * VP + cb + p1]       = s1;
                s2m[(r0l + 8) * VP + cb + p0] = s2;
                s2m[(r0l + 8) * VP + cb + p1] = s3;
                zp0 += s0 + s1;
                zp1 += s2 + s3;
            }
            atomicAdd(&zsh[r0l], zp0);
            atomicAdd(&zsh[r0l + 8], zp1);
        }
        __syncthreads();

        // ---- O += S2 @ V (1-pass tf32; permuted layouts, LDS.64 only) ----
        const float2* sf = (const float2*)s2m;                // pitch 36
        const float2* vf = (const float2*)vt + buf * 128 * (VP / 2);
#pragma unroll 2
        for (int k8 = 0; k8 < 8; k8++) {
            const int fo = k8 * 4 + (lane & 3);
            uint32_t a[2][4];
#pragma unroll
            for (int mt = 0; mt < 2; mt++) {
                const int r = wmO + mt * 16 + (lane >> 2);
                float2 f0 = sf[r * (VP / 2) + fo];
                float2 f1 = sf[(r + 8) * (VP / 2) + fo];
                a[mt][0] = __float_as_uint(f0.x);
                a[mt][1] = __float_as_uint(f1.x);
                a[mt][2] = __float_as_uint(f0.y);
                a[mt][3] = __float_as_uint(f1.y);
            }
#pragma unroll
            for (int nt = 0; nt < 4; nt++) {
                const int n = wnO + nt * 8 + (lane >> 2);
                float2 b2 = vf[n * (VP / 2) + fo];
                uint32_t b[2] = {__float_as_uint(b2.x), __float_as_uint(b2.y)};
#pragma unroll
                for (int mt = 0; mt < 2; mt++)
                    mma_tf32(oacc[mt][nt], a[mt], b, oacc[mt][nt]);
            }
        }
    }

    // ---- epilogue: divide by (z + eps), store ----
#pragma unroll
    for (int mt = 0; mt < 2; mt++) {
        const int rl = wmO + mt * 16 + (lane >> 2);
        const float inv0 = 1.0f / (zsh[rl] + 1e-5f);
        const float inv1 = 1.0f / (zsh[rl + 8] + 1e-5f);
        float* o0 = g_o + (size_t)(q0 + rl) * CH + h * HD;
        float* o1 = g_o + (size_t)(q0 + rl + 8) * CH + h * HD;
#pragma unroll
        for (int nt = 0; nt < 4; nt++) {
            const int cl = wnO + nt * 8 + 2 * (lane & 3);
            *(float2*)(o0 + cl) = make_float2(oacc[mt][nt][0] * inv0,
                                              oacc[mt][nt][1] * inv0);
            *(float2*)(o1 + cl) = make_float2(oacc[mt][nt][2] * inv1,
                                              oacc[mt][nt][3] * inv1);
        }
    }
}

// ---------------------------------------------------------------------------
extern "C" void kernel_launch(void* const* d_in, const int* in_sizes, int n_in,
                              void* d_out, int out_size) {
    const float* X     = (const float*)d_in[0];
    const float* Wq    = (const float*)d_in[1];
    const float* Wk    = (const float*)d_in[2];
    const float* Wv    = (const float*)d_in[3];
    const float* Wo    = (const float*)d_in[4];
    const float* gamma = (const float*)d_in[5];
    const float* beta  = (const float*)d_in[6];
    float* out = (float*)d_out;

    float *q, *k, *v, *o, *xp, *wqp, *wkp, *wvp, *wop, *op;
    cudaGetSymbolAddress((void**)&q, g_q);
    cudaGetSymbolAddress((void**)&k, g_k);
    cudaGetSymbolAddress((void**)&v, g_v);
    cudaGetSymbolAddress((void**)&o, g_o);
    cudaGetSymbolAddress((void**)&xp, g_xp);
    cudaGetSymbolAddress((void**)&wqp, g_wqp);
    cudaGetSymbolAddress((void**)&wkp, g_wkp);
    cudaGetSymbolAddress((void**)&wvp, g_wvp);
    cudaGetSymbolAddress((void**)&wop, g_wop);
    cudaGetSymbolAddress((void**)&op, g_op);

    cudaFuncSetAttribute(rebased_attn_mma,
                         cudaFuncAttributeMaxDynamicSharedMemorySize, ATTN_SMEM5);
    cudaFuncSetAttribute(rebased_attn_mma,
                         cudaFuncAttributePreferredSharedMemoryCarveout, 100);
    cudaFuncSetAttribute(mma_gemm_p,
                         cudaFuncAttributeMaxDynamicSharedMemorySize, GEMM_DSMEM);

    dim3 b256(256);
    const int NGRP = TSEQ * CH / 8;

    // pre-round + K-group permute: X, Wq, Wk, Wv, Wo
    round_permute5<<<dim3(NGRP / 256, 5), b256>>>(
        X, Wq, Wk, Wv, Wo, xp, wqp, wkp, wvp, wop, 5);

    // fused Q/K/V projections (v output tf32-rounded in epilogue)
    mma_gemm_p<<<dim3(16, 16, 3), b256, GEMM_DSMEM>>>(
        xp, wqp, wkp, wvp, q, k, v, 2);

    // feature map (q scaled by D^-0.5, k unscaled; rounded + permuted out)
    featmap<<<dim3(TSEQ * NH / 8, 2), b256>>>(gamma, beta);

    // causal quadratic attention (R9 frame + zero-cvt LDS.64 layouts)
    rebased_attn_mma<<<dim3(TSEQ / 64, NH), b256, ATTN_SMEM5>>>();

    // round+permute attention output, then O projection
    round_permute5<<<dim3(NGRP / 256, 1), b256>>>(
        o, o, o, o, o, op, op, op, op, op, 1);
    mma_gemm_p<<<dim3(16, 16, 1), b256, GEMM_DSMEM>>>(
        op, wop, wop, wop, out, out, out, -1);
}

// round 13
// speedup vs baseline: 1.2127x; 1.0175x over previous
#include <cuda_runtime.h>
#include <cstdint>

#define TSEQ 2048
#define CH   2048
#define NH   16
#define HD   128

// Scratch (allocation-free rule: __device__ globals)
__device__ float g_q[TSEQ * CH];
__device__ float g_k[TSEQ * CH];
__device__ float g_v[TSEQ * CH];
__device__ float g_o[TSEQ * CH];
// tf32-rounded, K-group-permuted operands
__device__ float g_xp[TSEQ * CH];
__device__ float g_wqp[CH * CH];
__device__ float g_wkp[CH * CH];
__device__ float g_wvp[CH * CH];
__device__ float g_wop[CH * CH];
__device__ float g_op[TSEQ * CH];

// ===========================================================================
// helpers
// ===========================================================================
__device__ __forceinline__ uint32_t smem_to_u32(const void* p) {
    uint32_t a;
    asm("{ .reg .u64 t; cvta.to.shared.u64 t, %1; cvt.u32.u64 %0, t; }"
        : "=r"(a) : "l"(p));
    return a;
}

__device__ __forceinline__ void cp_async16(uint32_t dst, const void* src) {
    asm volatile("cp.async.cg.shared.global [%0], [%1], 16;"
                 :: "r"(dst), "l"(src) : "memory");
}
#define CP_COMMIT() asm volatile("cp.async.commit_group;" ::: "memory")
#define CP_WAIT0()  asm volatile("cp.async.wait_group 0;" ::: "memory")

__device__ __forceinline__ uint32_t f2tf32(float x) {
    uint32_t r;
    asm("cvt.rna.tf32.f32 %0, %1;" : "=r"(r) : "f"(x));
    return r;
}
__device__ __forceinline__ float tf32r(float x) {
    return __uint_as_float(f2tf32(x));
}

// D = A @ B + C, m16n8k8 tf32, row.col
__device__ __forceinline__ void mma_tf32(float* d, const uint32_t* a,
                                         const uint32_t* b, const float* c) {
    asm volatile(
        "mma.sync.aligned.m16n8k8.row.col.f32.tf32.tf32.f32 "
        "{%0,%1,%2,%3}, {%4,%5,%6,%7}, {%8,%9}, {%10,%11,%12,%13};"
        : "=f"(d[0]), "=f"(d[1]), "=f"(d[2]), "=f"(d[3])
        : "r"(a[0]), "r"(a[1]), "r"(a[2]), "r"(a[3]),
          "r"(b[0]), "r"(b[1]),
          "f"(c[0]), "f"(c[1]), "f"(c[2]), "f"(c[3]));
}

// ===========================================================================
// round-to-tf32 + permute each 8-col K-group to [0,4,1,5,2,6,3,7]
// ===========================================================================
__global__ __launch_bounds__(256) void round_permute5(
    const float* __restrict__ s0, const float* __restrict__ s1,
    const float* __restrict__ s2, const float* __restrict__ s3,
    const float* __restrict__ s4,
    float* __restrict__ d0, float* __restrict__ d1, float* __restrict__ d2,
    float* __restrict__ d3, float* __restrict__ d4, int nmat) {
    const int i = blockIdx.x * blockDim.x + threadIdx.x;
    const int m = blockIdx.y;
    if (m >= nmat) return;
    const float* s = (m == 0) ? s0 : (m == 1) ? s1 : (m == 2) ? s2
                   : (m == 3) ? s3 : s4;
    float* d = (m == 0) ? d0 : (m == 1) ? d1 : (m == 2) ? d2
             : (m == 3) ? d3 : d4;
    float4 a = *(const float4*)(s + (size_t)i * 8);
    float4 b = *(const float4*)(s + (size_t)i * 8 + 4);
    float4 o0 = make_float4(tf32r(a.x), tf32r(b.x), tf32r(a.y), tf32r(b.y));
    float4 o1 = make_float4(tf32r(a.z), tf32r(b.z), tf32r(a.w), tf32r(b.w));
    *(float4*)(d + (size_t)i * 8)     = o0;
    *(float4*)(d + (size_t)i * 8 + 4) = o1;
}

// ===========================================================================
// C[M,N] = A[M,K] @ B[N,K]^T  (2048^3) via tf32 mma.sync (verified R7)
// roundz: blockIdx.z whose output is tf32-rounded at store (-1 = none)
// ===========================================================================
#define BK    16
#define LDS_P 24
#define P2    12
#define NTIL  (CH / BK)
#define GEMM_DSMEM (2 * 128 * LDS_P * 4 * 2)

__global__ __launch_bounds__(256, 2) void mma_gemm_p(
    const float* __restrict__ A,
    const float* __restrict__ B0, const float* __restrict__ B1,
    const float* __restrict__ B2,
    float* __restrict__ C0, float* __restrict__ C1, float* __restrict__ C2,
    int roundz) {
    extern __shared__ __align__(16) float gsm[];
    float* As = gsm;
    float* Bs = gsm + 2 * 128 * LDS_P;

    const float* B = (blockIdx.z == 0) ? B0 : (blockIdx.z == 1) ? B1 : B2;
    float*       C = (blockIdx.z == 0) ? C0 : (blockIdx.z == 1) ? C1 : C2;
    const bool rnd = ((int)blockIdx.z == roundz);

    const int tid  = threadIdx.x;
    const int lane = tid & 31;
    const int wid  = tid >> 5;
    const int wm   = (wid & 1) * 64;
    const int wn   = (wid >> 1) * 32;

    const int m0 = blockIdx.y * 128;
    const int n0 = blockIdx.x * 128;
    const float* Ab = A + (size_t)m0 * CH;
    const float* Bb = B + (size_t)n0 * CH;

    const uint32_t sA0 = smem_to_u32(As);
    const uint32_t sB0 = smem_to_u32(Bs);

    const int r0c = tid >> 2;
    const int c4  = (tid & 3) << 2;

    float acc[4][4][4];
#pragma unroll
    for (int mt = 0; mt < 4; mt++)
#pragma unroll
        for (int nt = 0; nt < 4; nt++)
#pragma unroll
            for (int e = 0; e < 4; e++) acc[mt][nt][e] = 0.f;

#pragma unroll
    for (int i = 0; i < 2; i++) {
        int row = r0c + i * 64;
        uint32_t off = (uint32_t)(row * LDS_P + c4) * 4u;
        cp_async16(sA0 + off, Ab + (size_t)row * CH + c4);
        cp_async16(sB0 + off, Bb + (size_t)row * CH + c4);
    }
    CP_COMMIT();

    for (int kt = 0; kt < NTIL; kt++) {
        CP_WAIT0();
        __syncthreads();

        if (kt + 1 < NTIL) {
            const int nbuf = (kt + 1) & 1;
            const int kc   = (kt + 1) * BK;
            const uint32_t sAd = sA0 + (uint32_t)(nbuf * 128 * LDS_P * 4);
            const uint32_t sBd = sB0 + (uint32_t)(nbuf * 128 * LDS_P * 4);
#pragma unroll
            for (int i = 0; i < 2; i++) {
                int row = r0c + i * 64;
                uint32_t off = (uint32_t)(row * LDS_P + c4) * 4u;
                cp_async16(sAd + off, Ab + (size_t)row * CH + kc + c4);
                cp_async16(sBd + off, Bb + (size_t)row * CH + kc + c4);
            }
            CP_COMMIT();
        }

        const int buf = kt & 1;
        const float2* Asb = (const float2*)(As + buf * 128 * LDS_P);
        const float2* Bsb = (const float2*)(Bs + buf * 128 * LDS_P);
#pragma unroll
        for (int ks = 0; ks < 2; ks++) {
            const int jq = ks * 4 + (lane & 3);
            uint32_t af[4][4], bf[4][2];
#pragma unroll
            for (int mt = 0; mt < 4; mt++) {
                int r = wm + mt * 16 + (lane >> 2);
                float2 f0 = Asb[r * P2 + jq];
                float2 f1 = Asb[(r + 8) * P2 + jq];
                af[mt][0] = __float_as_uint(f0.x);
                af[mt][1] = __float_as_uint(f1.x);
                af[mt][2] = __float_as_uint(f0.y);
                af[mt][3] = __float_as_uint(f1.y);
            }
#pragma unroll
            for (int nt = 0; nt < 4; nt++) {
                int cidx = wn + nt * 8 + (lane >> 2);
                float2 f = Bsb[cidx * P2 + jq];
                bf[nt][0] = __float_as_uint(f.x);
                bf[nt][1] = __float_as_uint(f.y);
            }
#pragma unroll
            for (int mt = 0; mt < 4; mt++)
#pragma unroll
                for (int nt = 0; nt < 4; nt++)
                    mma_tf32(acc[mt][nt], af[mt], bf[nt], acc[mt][nt]);
        }
        __syncthreads();
    }

#pragma unroll
    for (int mt = 0; mt < 4; mt++) {
        int r = m0 + wm + mt * 16 + (lane >> 2);
#pragma unroll
        for (int nt = 0; nt < 4; nt++) {
            int cidx = n0 + wn + nt * 8 + 2 * (lane & 3);
            float v0 = acc[mt][nt][0], v1 = acc[mt][nt][1];
            float v2 = acc[mt][nt][2], v3 = acc[mt][nt][3];
            if (rnd) { v0 = tf32r(v0); v1 = tf32r(v1);
                       v2 = tf32r(v2); v3 = tf32r(v3); }
            *(float2*)(C + (size_t)r * CH + cidx)       = make_float2(v0, v1);
            *(float2*)(C + (size_t)(r + 8) * CH + cidx) = make_float2(v2, v3);
        }
    }
}

// ---------------------------------------------------------------------------
// ReBased feature map; output tf32-rounded AND k-group-permuted
// [0,4,1,5,2,6,3,7] (validated: rel_err identical to fp32-store path).
// ---------------------------------------------------------------------------
__global__ __launch_bounds__(256) void featmap(const float* __restrict__ gamma,
                                               const float* __restrict__ beta) {
    const int warp = threadIdx.x >> 5;
    const int lane = threadIdx.x & 31;
    const int row  = blockIdx.x * 8 + warp;
    float* base = (blockIdx.y == 0) ? g_q : g_k;
    const float scale = (blockIdx.y == 0) ? 0.08838834764831845f : 1.0f;
    const int t = row >> 4;
    const int h = row & 15;
    float* p = base + (size_t)t * CH + h * HD;

    float x[4];
    float s = 0.f, sq = 0.f;
#pragma unroll
    for (int r = 0; r < 4; r++) {
        int d = lane + 32 * r;
        float y = p[d] * gamma[d] + beta[d];
        x[r] = y;
        s  += y;
        sq += y * y;
    }
#pragma unroll
    for (int o = 16; o; o >>= 1) {
        s  += __shfl_xor_sync(0xFFFFFFFFu, s, o);   // also orders reads < writes
        sq += __shfl_xor_sync(0xFFFFFFFFu, sq, o);
    }
    const float mu  = s * (1.0f / HD);
    const float var = sq * (1.0f / HD) - mu * mu;
    const float rs  = rsqrtf(var + 1e-5f) * scale;
#pragma unroll
    for (int r = 0; r < 4; r++) {
        int d = lane + 32 * r;
        int pos = (d & ~7) | ((d & 3) << 1) | ((d >> 2) & 1);
        p[pos] = tf32r((x[r] - mu) * rs);
    }
}

// ===========================================================================
// Causal quadratic attention v6 — software-pipelined: phase kt executes
// SV(kt) AND QK(kt+1) in one barrier-free stretch (independent buffers),
// ONE __syncthreads per k-tile. Zero-cvt permuted layouts (validated R12),
// conflict-free pitches (68/36 float2 ≡ 4 mod 16).
// QK warp tile 32x16 (2x4), SV 32x32. cp.async double-buffered k,
// register-prefetched v, s2m double-buffered.
// smem: qs[64][136] | ks[2][64][136] | vt[2][128][72] | s2m[2][64][72] | z[64]
// = 215,296 B  (1 CTA/SM)
// ===========================================================================
#define QP 136   // q/k float pitch  (68 float2)
#define VP 72    // vt/s2m float pitch (36 float2)
#define ATTN_SMEM6 ((64*QP + 2*64*QP + 2*128*VP + 2*64*VP + 64) * 4)

// QK: S = q.k^T (1-pass tf32), square+mask, store tf32-rounded permuted s2,
// z-atomics on the SAME rounded values. (index maps verified R12)
__device__ __forceinline__ void qk_step(const float2* __restrict__ qf,
                                        const float2* __restrict__ kf,
                                        float* __restrict__ s2d,
                                        float* __restrict__ zsh,
                                        int wmQ, int wnQ, int lane, bool diag) {
    float sacc[2][2][4];
#pragma unroll
    for (int mt = 0; mt < 2; mt++)
#pragma unroll
        for (int nt = 0; nt < 2; nt++)
#pragma unroll
            for (int e = 0; e < 4; e++) sacc[mt][nt][e] = 0.f;

#pragma unroll 4
    for (int k8 = 0; k8 < 16; k8++) {
        const int fo = k8 * 4 + (lane & 3);
        uint32_t af[2][4], bf[2][2];
#pragma unroll
        for (int mt = 0; mt < 2; mt++) {
            const int r = wmQ + mt * 16 + (lane >> 2);
            float2 f0 = qf[r * (QP / 2) + fo];
            float2 f1 = qf[(r + 8) * (QP / 2) + fo];
            af[mt][0] = __float_as_uint(f0.x);
            af[mt][1] = __float_as_uint(f1.x);
            af[mt][2] = __float_as_uint(f0.y);
            af[mt][3] = __float_as_uint(f1.y);
        }
#pragma unroll
        for (int nt = 0; nt < 2; nt++) {
            const int n = wnQ + nt * 8 + (lane >> 2);
            float2 f = kf[n * (QP / 2) + fo];
            bf[nt][0] = __float_as_uint(f.x);
            bf[nt][1] = __float_as_uint(f.y);
        }
#pragma unroll
        for (int mt = 0; mt < 2; mt++)
#pragma unroll
            for (int nt = 0; nt < 2; nt++)
                mma_tf32(sacc[mt][nt], af[mt], bf[nt], sacc[mt][nt]);
    }

    const int j  = lane & 3;
    const int p0 = (j < 2) ? 4 * j : 4 * j - 7;
    const int p1 = (j < 2) ? 4 * j + 2 : 4 * j - 5;
#pragma unroll
    for (int mt = 0; mt < 2; mt++) {
        const int r0l = wmQ + mt * 16 + (lane >> 2);
        float zp0 = 0.f, zp1 = 0.f;
#pragma unroll
        for (int nt = 0; nt < 2; nt++) {
            const int cb  = wnQ + nt * 8;
            const int c0l = cb + 2 * j;
            float s0 = sacc[mt][nt][0]; s0 *= s0;
            float s1 = sacc[mt][nt][1]; s1 *= s1;
            float s2 = sacc[mt][nt][2]; s2 *= s2;
            float s3 = sacc[mt][nt][3]; s3 *= s3;
            if (diag) {
                if (c0l > r0l)         s0 = 0.f;
                if (c0l + 1 > r0l)     s1 = 0.f;
                if (c0l > r0l + 8)     s2 = 0.f;
                if (c0l + 1 > r0l + 8) s3 = 0.f;
            }
            s0 = tf32r(s0); s1 = tf32r(s1); s2 = tf32r(s2); s3 = tf32r(s3);
            s2d[r0l * VP + cb + p0]       = s0;
            s2d[r0l * VP + cb + p1]       = s1;
            s2d[(r0l + 8) * VP + cb + p0] = s2;
            s2d[(r0l + 8) * VP + cb + p1] = s3;
            zp0 += s0 + s1;
            zp1 += s2 + s3;
        }
        atomicAdd(&zsh[r0l], zp0);
        atomicAdd(&zsh[r0l + 8], zp1);
    }
}

// SV: O += S2 @ V (1-pass tf32, permuted layouts)
__device__ __forceinline__ void sv_step(const float2* __restrict__ sf,
                                        const float2* __restrict__ vf,
                                        float (&oacc)[2][4][4],
                                        int wmO, int wnO, int lane) {
#pragma unroll 2
    for (int k8 = 0; k8 < 8; k8++) {
        const int fo = k8 * 4 + (lane & 3);
        uint32_t a[2][4];
#pragma unroll
        for (int mt = 0; mt < 2; mt++) {
            const int r = wmO + mt * 16 + (lane >> 2);
            float2 f0 = sf[r * (VP / 2) + fo];
            float2 f1 = sf[(r + 8) * (VP / 2) + fo];
            a[mt][0] = __float_as_uint(f0.x);
            a[mt][1] = __float_as_uint(f1.x);
            a[mt][2] = __float_as_uint(f0.y);
            a[mt][3] = __float_as_uint(f1.y);
        }
#pragma unroll
        for (int nt = 0; nt < 4; nt++) {
            const int n = wnO + nt * 8 + (lane >> 2);
            float2 b2 = vf[n * (VP / 2) + fo];
            uint32_t b[2] = {__float_as_uint(b2.x), __float_as_uint(b2.y)};
#pragma unroll
            for (int mt = 0; mt < 2; mt++)
                mma_tf32(oacc[mt][nt], a[mt], b, oacc[mt][nt]);
        }
    }
}

__global__ __launch_bounds__(256, 1) void rebased_attn_mma() {
    extern __shared__ __align__(16) float asm_[];
    float* qs  = asm_;                      // [64][QP]
    float* ks  = qs + 64 * QP;              // [2][64][QP]
    float* vt  = ks + 2 * 64 * QP;          // [2][128][VP]
    float* s2m = vt + 2 * 128 * VP;         // [2][64][VP]
    float* zsh = s2m + 2 * 64 * VP;         // [64]

    const int tid  = threadIdx.x;
    const int lane = tid & 31;
    const int wid  = tid >> 5;
    const int qt   = 31 - blockIdx.x;       // heavy tiles first
    const int h    = blockIdx.y;
    const int q0   = qt * 64;

    const int wmQ = (wid & 1) * 32, wnQ = (wid >> 1) * 16;  // QK 32x16
    const int wmO = (wid & 1) * 32, wnO = (wid >> 1) * 32;  // SV 32x32

    const uint32_t qs_u = smem_to_u32(qs);
    const uint32_t ks_u = smem_to_u32(ks);

    // v prefetch slice: 32 floats per thread (verified R12 map)
    const int vj  = tid & 63;
    const int vdb = (tid >> 6) * 4;
    const int vw  = vj & 7;
    const int pj  = (vj & ~7) + ((vw < 4) ? vw * 2 : (vw - 4) * 2 + 1);

    // ---- prologue: cp.async q tile + k tile 0 ----
#pragma unroll
    for (int i = 0; i < 8; i++) {
        const int idx = tid + i * 256;
        const int r = idx >> 5, c = idx & 31;
        cp_async16(qs_u + (uint32_t)(r * QP + c * 4) * 4u,
                   g_q + (size_t)(q0 + r) * CH + h * HD + c * 4);
        cp_async16(ks_u + (uint32_t)(r * QP + c * 4) * 4u,
                   g_k + (size_t)r * CH + h * HD + c * 4);
    }
    CP_COMMIT();

    float4 vr[8];
    {
        const float* vs = g_v + (size_t)vj * CH + h * HD;
#pragma unroll
        for (int c = 0; c < 8; c++) vr[c] = *(const float4*)(vs + vdb + c * 16);
    }
    if (tid < 64) zsh[tid] = 0.f;

    float oacc[2][4][4];
#pragma unroll
    for (int mt = 0; mt < 2; mt++)
#pragma unroll
        for (int nt = 0; nt < 4; nt++)
#pragma unroll
            for (int e = 0; e < 4; e++) oacc[mt][nt][e] = 0.f;

    CP_WAIT0();
    __syncthreads();   // q, ks[0], zsh ready

    // ---- pre-phase: store vt[0]; prefetch k1/v1; QK(0) -> s2m[0] ----
    {
        float* vtb = vt;   // buf 0
#pragma unroll
        for (int c = 0; c < 8; c++) {
            const int d0 = vdb + c * 16;
            vtb[(d0 + 0) * VP + pj] = vr[c].x;
            vtb[(d0 + 1) * VP + pj] = vr[c].y;
            vtb[(d0 + 2) * VP + pj] = vr[c].z;
            vtb[(d0 + 3) * VP + pj] = vr[c].w;
        }
    }
    if (qt > 0) {
        const uint32_t kd = ks_u + (uint32_t)(64 * QP * 4);
#pragma unroll
        for (int i = 0; i < 8; i++) {
            const int idx = tid + i * 256;
            const int r = idx >> 5, c = idx & 31;
            cp_async16(kd + (uint32_t)(r * QP + c * 4) * 4u,
                       g_k + (size_t)(64 + r) * CH + h * HD + c * 4);
        }
        CP_COMMIT();
        const float* vs = g_v + (size_t)(64 + vj) * CH + h * HD;
#pragma unroll
        for (int c = 0; c < 8; c++) vr[c] = *(const float4*)(vs + vdb + c * 16);
    }
    qk_step((const float2*)qs, (const float2*)ks, s2m, zsh,
            wmQ, wnQ, lane, qt == 0);
    if (qt > 0) CP_WAIT0();
    __syncthreads();   // s2m[0], vt[0], ks[1] visible

    // ---- pipelined main loop: ONE barrier per k-tile ----
    for (int kt = 0; kt <= qt; kt++) {
        const int buf = kt & 1, nbuf = buf ^ 1;

        if (kt < qt) {
            // store v(kt+1) into vt[nbuf]
            {
                float* vtb = vt + nbuf * 128 * VP;
#pragma unroll
                for (int c = 0; c < 8; c++) {
                    const int d0 = vdb + c * 16;
                    vtb[(d0 + 0) * VP + pj] = vr[c].x;
                    vtb[(d0 + 1) * VP + pj] = vr[c].y;
                    vtb[(d0 + 2) * VP + pj] = vr[c].z;
                    vtb[(d0 + 3) * VP + pj] = vr[c].w;
                }
            }
            // prefetch k(kt+2) into ks[buf] + v(kt+2) into regs
            if (kt + 2 <= qt) {
                const int kn = (kt + 2) * 64;
                const uint32_t kd = ks_u + (uint32_t)(buf * 64 * QP * 4);
#pragma unroll
                for (int i = 0; i < 8; i++) {
                    const int idx = tid + i * 256;
                    const int r = idx >> 5, c = idx & 31;
                    cp_async16(kd + (uint32_t)(r * QP + c * 4) * 4u,
                               g_k + (size_t)(kn + r) * CH + h * HD + c * 4);
                }
                CP_COMMIT();
                const float* vs = g_v + (size_t)(kn + vj) * CH + h * HD;
#pragma unroll
                for (int c = 0; c < 8; c++)
                    vr[c] = *(const float4*)(vs + vdb + c * 16);
            }
            // QK(kt+1): independent of SV(kt) below — fills the pipe
            qk_step((const float2*)qs,
                    (const float2*)(ks + nbuf * 64 * QP),
                    s2m + nbuf * 64 * VP, zsh,
                    wmQ, wnQ, lane, (kt + 1) == qt);
        }

        // SV(kt)
        sv_step((const float2*)(s2m + buf * 64 * VP),
                (const float2*)(vt + buf * 128 * VP),
                oacc, wmO, wnO, lane);

        if (kt < qt) {
            if (kt + 2 <= qt) CP_WAIT0();
            __syncthreads();   // s2m[nbuf], vt[nbuf], ks[buf] visible
        }
    }

    // ---- epilogue: divide by (z + eps), store ----
    // (last z atomics were in phase qt-1, barrier-separated from here)
#pragma unroll
    for (int mt = 0; mt < 2; mt++) {
        const int rl = wmO + mt * 16 + (lane >> 2);
        const float inv0 = 1.0f / (zsh[rl] + 1e-5f);
        const float inv1 = 1.0f / (zsh[rl + 8] + 1e-5f);
        float* o0 = g_o + (size_t)(q0 + rl) * CH + h * HD;
        float* o1 = g_o + (size_t)(q0 + rl + 8) * CH + h * HD;
#pragma unroll
        for (int nt = 0; nt < 4; nt++) {
            const int cl = wnO + nt * 8 + 2 * (lane & 3);
            *(float2*)(o0 + cl) = make_float2(oacc[mt][nt][0] * inv0,
                                              oacc[mt][nt][1] * inv0);
            *(float2*)(o1 + cl) = make_float2(oacc[mt][nt][2] * inv1,
                                              oacc[mt][nt][3] * inv1);
        }
    }
}

// ---------------------------------------------------------------------------
extern "C" void kernel_launch(void* const* d_in, const int* in_sizes, int n_in,
                              void* d_out, int out_size) {
    const float* X     = (const float*)d_in[0];
    const float* Wq    = (const float*)d_in[1];
    const float* Wk    = (const float*)d_in[2];
    const float* Wv    = (const float*)d_in[3];
    const float* Wo    = (const float*)d_in[4];
    const float* gamma = (const float*)d_in[5];
    const float* beta  = (const float*)d_in[6];
    float* out = (float*)d_out;

    float *q, *k, *v, *o, *xp, *wqp, *wkp, *wvp, *wop, *op;
    cudaGetSymbolAddress((void**)&q, g_q);
    cudaGetSymbolAddress((void**)&k, g_k);
    cudaGetSymbolAddress((void**)&v, g_v);
    cudaGetSymbolAddress((void**)&o, g_o);
    cudaGetSymbolAddress((void**)&xp, g_xp);
    cudaGetSymbolAddress((void**)&wqp, g_wqp);
    cudaGetSymbolAddress((void**)&wkp, g_wkp);
    cudaGetSymbolAddress((void**)&wvp, g_wvp);
    cudaGetSymbolAddress((void**)&wop, g_wop);
    cudaGetSymbolAddress((void**)&op, g_op);

    cudaFuncSetAttribute(rebased_attn_mma,
                         cudaFuncAttributeMaxDynamicSharedMemorySize, ATTN_SMEM6);
    cudaFuncSetAttribute(rebased_attn_mma,
                         cudaFuncAttributePreferredSharedMemoryCarveout, 100);
    cudaFuncSetAttribute(mma_gemm_p,
                         cudaFuncAttributeMaxDynamicSharedMemorySize, GEMM_DSMEM);

    dim3 b256(256);
    const int NGRP = TSEQ * CH / 8;

    // pre-round + K-group permute: X, Wq, Wk, Wv, Wo
    round_permute5<<<dim3(NGRP / 256, 5), b256>>>(
        X, Wq, Wk, Wv, Wo, xp, wqp, wkp, wvp, wop, 5);

    // fused Q/K/V projections (v output tf32-rounded in epilogue)
    mma_gemm_p<<<dim3(16, 16, 3), b256, GEMM_DSMEM>>>(
        xp, wqp, wkp, wvp, q, k, v, 2);

    // feature map (q scaled by D^-0.5, k unscaled; rounded + permuted out)
    featmap<<<dim3(TSEQ * NH / 8, 2), b256>>>(gamma, beta);

    // causal quadratic attention (software-pipelined, 1 barrier/k-tile)
    rebased_attn_mma<<<dim3(TSEQ / 64, NH), b256, ATTN_SMEM6>>>();

    // round+permute attention output, then O projection
    round_permute5<<<dim3(NGRP / 256, 1), b256>>>(
        o, o, o, o, o, op, op, op, op, op, 1);
    mma_gemm_p<<<dim3(16, 16, 1), b256, GEMM_DSMEM>>>(
        op, wop, wop, wop, out, out, out, -1);
}

// round 14
// speedup vs baseline: 1.2179x; 1.0043x over previous
#include <cuda_runtime.h>
#include <cstdint>

#define TSEQ 2048
#define CH   2048
#define NH   16
#define HD   128

// Scratch (allocation-free rule: __device__ globals)
__device__ float g_q[TSEQ * CH];
__device__ float g_k[TSEQ * CH];
__device__ float g_v[TSEQ * CH];
__device__ float g_o[TSEQ * CH];
// tf32-rounded, K-group-permuted operands
__device__ float g_xp[TSEQ * CH];
__device__ float g_wqp[CH * CH];
__device__ float g_wkp[CH * CH];
__device__ float g_wvp[CH * CH];
__device__ float g_wop[CH * CH];
__device__ float g_op[TSEQ * CH];

// ===========================================================================
// helpers
// ===========================================================================
__device__ __forceinline__ uint32_t smem_to_u32(const void* p) {
    uint32_t a;
    asm("{ .reg .u64 t; cvta.to.shared.u64 t, %1; cvt.u32.u64 %0, t; }"
        : "=r"(a) : "l"(p));
    return a;
}

__device__ __forceinline__ void cp_async16(uint32_t dst, const void* src) {
    asm volatile("cp.async.cg.shared.global [%0], [%1], 16;"
                 :: "r"(dst), "l"(src) : "memory");
}
#define CP_COMMIT() asm volatile("cp.async.commit_group;" ::: "memory")
#define CP_WAIT0()  asm volatile("cp.async.wait_group 0;" ::: "memory")

__device__ __forceinline__ uint32_t f2tf32(float x) {
    uint32_t r;
    asm("cvt.rna.tf32.f32 %0, %1;" : "=r"(r) : "f"(x));
    return r;
}
__device__ __forceinline__ float tf32r(float x) {
    return __uint_as_float(f2tf32(x));
}

// D = A @ B + C, m16n8k8 tf32, row.col
__device__ __forceinline__ void mma_tf32(float* d, const uint32_t* a,
                                         const uint32_t* b, const float* c) {
    asm volatile(
        "mma.sync.aligned.m16n8k8.row.col.f32.tf32.tf32.f32 "
        "{%0,%1,%2,%3}, {%4,%5,%6,%7}, {%8,%9}, {%10,%11,%12,%13};"
        : "=f"(d[0]), "=f"(d[1]), "=f"(d[2]), "=f"(d[3])
        : "r"(a[0]), "r"(a[1]), "r"(a[2]), "r"(a[3]),
          "r"(b[0]), "r"(b[1]),
          "f"(c[0]), "f"(c[1]), "f"(c[2]), "f"(c[3]));
}

// ===========================================================================
// round-to-tf32 + permute each 8-col K-group to [0,4,1,5,2,6,3,7]
// ===========================================================================
__global__ __launch_bounds__(256) void round_permute5(
    const float* __restrict__ s0, const float* __restrict__ s1,
    const float* __restrict__ s2, const float* __restrict__ s3,
    const float* __restrict__ s4,
    float* __restrict__ d0, float* __restrict__ d1, float* __restrict__ d2,
    float* __restrict__ d3, float* __restrict__ d4, int nmat) {
    const int i = blockIdx.x * blockDim.x + threadIdx.x;
    const int m = blockIdx.y;
    if (m >= nmat) return;
    const float* s = (m == 0) ? s0 : (m == 1) ? s1 : (m == 2) ? s2
                   : (m == 3) ? s3 : s4;
    float* d = (m == 0) ? d0 : (m == 1) ? d1 : (m == 2) ? d2
             : (m == 3) ? d3 : d4;
    float4 a = *(const float4*)(s + (size_t)i * 8);
    float4 b = *(const float4*)(s + (size_t)i * 8 + 4);
    float4 o0 = make_float4(tf32r(a.x), tf32r(b.x), tf32r(a.y), tf32r(b.y));
    float4 o1 = make_float4(tf32r(a.z), tf32r(b.z), tf32r(a.w), tf32r(b.w));
    *(float4*)(d + (size_t)i * 8)     = o0;
    *(float4*)(d + (size_t)i * 8 + 4) = o1;
}

// ===========================================================================
// C[M,N] = A[M,K] @ B[N,K]^T  (2048^3) via tf32 mma.sync (verified R7)
// roundz: blockIdx.z whose output is tf32-rounded at store (-1 = none)
// ===========================================================================
#define BK    16
#define LDS_P 24
#define P2    12
#define NTIL  (CH / BK)
#define GEMM_DSMEM (2 * 128 * LDS_P * 4 * 2)

__global__ __launch_bounds__(256, 2) void mma_gemm_p(
    const float* __restrict__ A,
    const float* __restrict__ B0, const float* __restrict__ B1,
    const float* __restrict__ B2,
    float* __restrict__ C0, float* __restrict__ C1, float* __restrict__ C2,
    int roundz) {
    extern __shared__ __align__(16) float gsm[];
    float* As = gsm;
    float* Bs = gsm + 2 * 128 * LDS_P;

    const float* B = (blockIdx.z == 0) ? B0 : (blockIdx.z == 1) ? B1 : B2;
    float*       C = (blockIdx.z == 0) ? C0 : (blockIdx.z == 1) ? C1 : C2;
    const bool rnd = ((int)blockIdx.z == roundz);

    const int tid  = threadIdx.x;
    const int lane = tid & 31;
    const int wid  = tid >> 5;
    const int wm   = (wid & 1) * 64;
    const int wn   = (wid >> 1) * 32;

    const int m0 = blockIdx.y * 128;
    const int n0 = blockIdx.x * 128;
    const float* Ab = A + (size_t)m0 * CH;
    const float* Bb = B + (size_t)n0 * CH;

    const uint32_t sA0 = smem_to_u32(As);
    const uint32_t sB0 = smem_to_u32(Bs);

    const int r0c = tid >> 2;
    const int c4  = (tid & 3) << 2;

    float acc[4][4][4];
#pragma unroll
    for (int mt = 0; mt < 4; mt++)
#pragma unroll
        for (int nt = 0; nt < 4; nt++)
#pragma unroll
            for (int e = 0; e < 4; e++) acc[mt][nt][e] = 0.f;

#pragma unroll
    for (int i = 0; i < 2; i++) {
        int row = r0c + i * 64;
        uint32_t off = (uint32_t)(row * LDS_P + c4) * 4u;
        cp_async16(sA0 + off, Ab + (size_t)row * CH + c4);
        cp_async16(sB0 + off, Bb + (size_t)row * CH + c4);
    }
    CP_COMMIT();

    for (int kt = 0; kt < NTIL; kt++) {
        CP_WAIT0();
        __syncthreads();

        if (kt + 1 < NTIL) {
            const int nbuf = (kt + 1) & 1;
            const int kc   = (kt + 1) * BK;
            const uint32_t sAd = sA0 + (uint32_t)(nbuf * 128 * LDS_P * 4);
            const uint32_t sBd = sB0 + (uint32_t)(nbuf * 128 * LDS_P * 4);
#pragma unroll
            for (int i = 0; i < 2; i++) {
                int row = r0c + i * 64;
                uint32_t off = (uint32_t)(row * LDS_P + c4) * 4u;
                cp_async16(sAd + off, Ab + (size_t)row * CH + kc + c4);
                cp_async16(sBd + off, Bb + (size_t)row * CH + kc + c4);
            }
            CP_COMMIT();
        }

        const int buf = kt & 1;
        const float2* Asb = (const float2*)(As + buf * 128 * LDS_P);
        const float2* Bsb = (const float2*)(Bs + buf * 128 * LDS_P);
#pragma unroll
        for (int ks = 0; ks < 2; ks++) {
            const int jq = ks * 4 + (lane & 3);
            uint32_t af[4][4], bf[4][2];
#pragma unroll
            for (int mt = 0; mt < 4; mt++) {
                int r = wm + mt * 16 + (lane >> 2);
                float2 f0 = Asb[r * P2 + jq];
                float2 f1 = Asb[(r + 8) * P2 + jq];
                af[mt][0] = __float_as_uint(f0.x);
                af[mt][1] = __float_as_uint(f1.x);
                af[mt][2] = __float_as_uint(f0.y);
                af[mt][3] = __float_as_uint(f1.y);
            }
#pragma unroll
            for (int nt = 0; nt < 4; nt++) {
                int cidx = wn + nt * 8 + (lane >> 2);
                float2 f = Bsb[cidx * P2 + jq];
                bf[nt][0] = __float_as_uint(f.x);
                bf[nt][1] = __float_as_uint(f.y);
            }
#pragma unroll
            for (int mt = 0; mt < 4; mt++)
#pragma unroll
                for (int nt = 0; nt < 4; nt++)
                    mma_tf32(acc[mt][nt], af[mt], bf[nt], acc[mt][nt]);
        }
        __syncthreads();
    }

#pragma unroll
    for (int mt = 0; mt < 4; mt++) {
        int r = m0 + wm + mt * 16 + (lane >> 2);
#pragma unroll
        for (int nt = 0; nt < 4; nt++) {
            int cidx = n0 + wn + nt * 8 + 2 * (lane & 3);
            float v0 = acc[mt][nt][0], v1 = acc[mt][nt][1];
            float v2 = acc[mt][nt][2], v3 = acc[mt][nt][3];
            if (rnd) { v0 = tf32r(v0); v1 = tf32r(v1);
                       v2 = tf32r(v2); v3 = tf32r(v3); }
            *(float2*)(C + (size_t)r * CH + cidx)       = make_float2(v0, v1);
            *(float2*)(C + (size_t)(r + 8) * CH + cidx) = make_float2(v2, v3);
        }
    }
}

// ---------------------------------------------------------------------------
// ReBased feature map; output tf32-rounded AND k-group-permuted
// [0,4,1,5,2,6,3,7] (validated: rel_err identical to fp32-store path).
// ---------------------------------------------------------------------------
__global__ __launch_bounds__(256) void featmap(const float* __restrict__ gamma,
                                               const float* __restrict__ beta) {
    const int warp = threadIdx.x >> 5;
    const int lane = threadIdx.x & 31;
    const int row  = blockIdx.x * 8 + warp;
    float* base = (blockIdx.y == 0) ? g_q : g_k;
    const float scale = (blockIdx.y == 0) ? 0.08838834764831845f : 1.0f;
    const int t = row >> 4;
    const int h = row & 15;
    float* p = base + (size_t)t * CH + h * HD;

    float x[4];
    float s = 0.f, sq = 0.f;
#pragma unroll
    for (int r = 0; r < 4; r++) {
        int d = lane + 32 * r;
        float y = p[d] * gamma[d] + beta[d];
        x[r] = y;
        s  += y;
        sq += y * y;
    }
#pragma unroll
    for (int o = 16; o; o >>= 1) {
        s  += __shfl_xor_sync(0xFFFFFFFFu, s, o);   // also orders reads < writes
        sq += __shfl_xor_sync(0xFFFFFFFFu, sq, o);
    }
    const float mu  = s * (1.0f / HD);
    const float var = sq * (1.0f / HD) - mu * mu;
    const float rs  = rsqrtf(var + 1e-5f) * scale;
#pragma unroll
    for (int r = 0; r < 4; r++) {
        int d = lane + 32 * r;
        int pos = (d & ~7) | ((d & 3) << 1) | ((d >> 2) & 1);
        p[pos] = tf32r((x[r] - mu) * rs);
    }
}

// ===========================================================================
// Causal quadratic attention v7 — 2 CTAs/SM (96.4 KB smem):
//   q-tile 32 rows x k-tile 64 rows, grid (64, 16) = 1024 CTAs.
//   v kept k-major [j][d] (no transpose, no extra buffer); SV B-operand
//   fetched as 2 conflict-free scalar LDS.32 (banks 8j+n, all distinct).
//   Zero-cvt permuted q/k/s2 layouts (validated R12), pitches 136/72.
//   Single-buffered k/v; cross-CTA overlap hides load waits + barriers.
// QK warp tile 32x8 (wnQ = wid*8); SV warp tile 32x16 (wnO = wid*16).
// smem: qs[32][136] | ks[64][136] | vs[64][136] | s2m[32][72] | z[32]
// = 96,384 B
// ===========================================================================
#define QP 136   // q/k/v float pitch (68 float2)
#define VP 72    // s2m float pitch (36 float2)
#define ATTN_SMEM7 ((32*QP + 64*QP + 64*QP + 32*VP + 32) * 4)

__global__ __launch_bounds__(256, 2) void rebased_attn_mma() {
    extern __shared__ __align__(16) float asm_[];
    float* qs  = asm_;                      // [32][QP]
    float* ks  = qs + 32 * QP;              // [64][QP]
    float* vs  = ks + 64 * QP;              // [64][QP]  (k-major, raw d order)
    float* s2m = vs + 64 * QP;              // [32][VP]
    float* zsh = s2m + 32 * VP;             // [32]

    const int tid  = threadIdx.x;
    const int lane = tid & 31;
    const int wid  = tid >> 5;
    const int qt   = 63 - blockIdx.x;       // heavy q32-tiles first
    const int h    = blockIdx.y;
    const int q0   = qt * 32;
    const int nk   = (qt >> 1) + 1;         // number of 64-row k-tiles

    const int wnQ = wid * 8;                // QK 32x8
    const int wnO = wid * 16;               // SV 32x16

    const uint32_t qs_u = smem_to_u32(qs);
    const uint32_t ks_u = smem_to_u32(ks);
    const uint32_t vs_u = smem_to_u32(vs);

    // ---- prologue: cp.async q tile (32x128 = 1024 chunks, 4/thread) ----
#pragma unroll
    for (int i = 0; i < 4; i++) {
        const int idx = tid + i * 256;
        const int r = idx >> 5, c = idx & 31;
        cp_async16(qs_u + (uint32_t)(r * QP + c * 4) * 4u,
                   g_q + (size_t)(q0 + r) * CH + h * HD + c * 4);
    }
    CP_COMMIT();
    if (tid < 32) zsh[tid] = 0.f;

    float oacc[2][2][4];
#pragma unroll
    for (int mt = 0; mt < 2; mt++)
#pragma unroll
        for (int nt = 0; nt < 2; nt++)
#pragma unroll
            for (int e = 0; e < 4; e++) oacc[mt][nt][e] = 0.f;

    const int j  = lane & 3;
    const int p0 = (j < 2) ? 4 * j : 4 * j - 7;
    const int p1 = (j < 2) ? 4 * j + 2 : 4 * j - 5;

    for (int kt = 0; kt < nk; kt++) {
        const int k0 = kt * 64;

        // ---- load k/v tile (ks/vs free: barrier at end of prev iter) ----
#pragma unroll
        for (int i = 0; i < 8; i++) {
            const int idx = tid + i * 256;
            const int r = idx >> 5, c = idx & 31;
            const uint32_t so = (uint32_t)(r * QP + c * 4) * 4u;
            cp_async16(ks_u + so, g_k + (size_t)(k0 + r) * CH + h * HD + c * 4);
            cp_async16(vs_u + so, g_v + (size_t)(k0 + r) * CH + h * HD + c * 4);
        }
        CP_COMMIT();
        CP_WAIT0();
        __syncthreads();   // q (iter 0), ks, vs ready; s2m free

        // ---- QK: S = q.k^T (1-pass tf32, LDS.64 only), square+mask,
        //      store tf32-rounded permuted s2, z sums the same values ----
        {
            const float2* qf = (const float2*)qs;        // pitch 68
            const float2* kf = (const float2*)ks;        // pitch 68
            float sacc[2][4];
#pragma unroll
            for (int mt = 0; mt < 2; mt++)
#pragma unroll
                for (int e = 0; e < 4; e++) sacc[mt][e] = 0.f;

#pragma unroll 4
            for (int k8 = 0; k8 < 16; k8++) {
                const int fo = k8 * 4 + (lane & 3);
                uint32_t bf[2];
                {
                    const int n = wnQ + (lane >> 2);
                    float2 f = kf[n * (QP / 2) + fo];
                    bf[0] = __float_as_uint(f.x);
                    bf[1] = __float_as_uint(f.y);
                }
#pragma unroll
                for (int mt = 0; mt < 2; mt++) {
                    const int r = mt * 16 + (lane >> 2);
                    float2 f0 = qf[r * (QP / 2) + fo];
                    float2 f1 = qf[(r + 8) * (QP / 2) + fo];
                    uint32_t af[4] = {__float_as_uint(f0.x), __float_as_uint(f1.x),
                                      __float_as_uint(f0.y), __float_as_uint(f1.y)};
                    mma_tf32(sacc[mt], af, bf, sacc[mt]);
                }
            }

            const bool diag = (kt == nk - 1);
            const int  off  = k0 - q0;        // col+off > row ⇒ masked
#pragma unroll
            for (int mt = 0; mt < 2; mt++) {
                const int r0l = mt * 16 + (lane >> 2);
                const int c0l = wnQ + 2 * j;
                float s0 = sacc[mt][0]; s0 *= s0;
                float s1 = sacc[mt][1]; s1 *= s1;
                float s2 = sacc[mt][2]; s2 *= s2;
                float s3 = sacc[mt][3]; s3 *= s3;
                if (diag) {
                    if (c0l + off > r0l)         s0 = 0.f;
                    if (c0l + 1 + off > r0l)     s1 = 0.f;
                    if (c0l + off > r0l + 8)     s2 = 0.f;
                    if (c0l + 1 + off > r0l + 8) s3 = 0.f;
                }
                s0 = tf32r(s0); s1 = tf32r(s1); s2 = tf32r(s2); s3 = tf32r(s3);
                s2m[r0l * VP + wnQ + p0]       = s0;
                s2m[r0l * VP + wnQ + p1]       = s1;
                s2m[(r0l + 8) * VP + wnQ + p0] = s2;
                s2m[(r0l + 8) * VP + wnQ + p1] = s3;
                atomicAdd(&zsh[r0l], s0 + s1);
                atomicAdd(&zsh[r0l + 8], s2 + s3);
            }
        }
        __syncthreads();   // s2m visible

        // ---- SV: O += S2 @ V (s2 via permuted LDS.64; v via 2 scalar
        //      conflict-free LDS.32 per fragment) ----
        {
            const float2* sf = (const float2*)s2m;       // pitch 36
#pragma unroll 2
            for (int k8 = 0; k8 < 8; k8++) {
                const int fo = k8 * 4 + (lane & 3);
                const int kq = k8 * 8 + (lane & 3);
                uint32_t a[2][4];
#pragma unroll
                for (int mt = 0; mt < 2; mt++) {
                    const int r = mt * 16 + (lane >> 2);
                    float2 f0 = sf[r * (VP / 2) + fo];
                    float2 f1 = sf[(r + 8) * (VP / 2) + fo];
                    a[mt][0] = __float_as_uint(f0.x);
                    a[mt][1] = __float_as_uint(f1.x);
                    a[mt][2] = __float_as_uint(f0.y);
                    a[mt][3] = __float_as_uint(f1.y);
                }
#pragma unroll
                for (int nt = 0; nt < 2; nt++) {
                    const int n = wnO + nt * 8 + (lane >> 2);
                    uint32_t b[2];
                    b[0] = __float_as_uint(vs[kq * QP + n]);
                    b[1] = __float_as_uint(vs[(kq + 4) * QP + n]);
#pragma unroll
                    for (int mt = 0; mt < 2; mt++)
                        mma_tf32(oacc[mt][nt], a[mt], b, oacc[mt][nt]);
                }
            }
        }
        __syncthreads();   // SV done: ks/vs/s2m reusable next iter
    }

    // ---- epilogue: divide by (z + eps), store ----
#pragma unroll
    for (int mt = 0; mt < 2; mt++) {
        const int rl = mt * 16 + (lane >> 2);
        const float inv0 = 1.0f / (zsh[rl] + 1e-5f);
        const float inv1 = 1.0f / (zsh[rl + 8] + 1e-5f);
        float* o0 = g_o + (size_t)(q0 + rl) * CH + h * HD;
        float* o1 = g_o + (size_t)(q0 + rl + 8) * CH + h * HD;
#pragma unroll
        for (int nt = 0; nt < 2; nt++) {
            const int cl = wnO + nt * 8 + 2 * (lane & 3);
            *(float2*)(o0 + cl) = make_float2(oacc[mt][nt][0] * inv0,
                                              oacc[mt][nt][1] * inv0);
            *(float2*)(o1 + cl) = make_float2(oacc[mt][nt][2] * inv1,
                                              oacc[mt][nt][3] * inv1);
        }
    }
}

// ---------------------------------------------------------------------------
extern "C" void kernel_launch(void* const* d_in, const int* in_sizes, int n_in,
                              void* d_out, int out_size) {
    const float* X     = (const float*)d_in[0];
    const float* Wq    = (const float*)d_in[1];
    const float* Wk    = (const float*)d_in[2];
    const float* Wv    = (const float*)d_in[3];
    const float* Wo    = (const float*)d_in[4];
    const float* gamma = (const float*)d_in[5];
    const float* beta  = (const float*)d_in[6];
    float* out = (float*)d_out;

    float *q, *k, *v, *o, *xp, *wqp, *wkp, *wvp, *wop, *op;
    cudaGetSymbolAddress((void**)&q, g_q);
    cudaGetSymbolAddress((void**)&k, g_k);
    cudaGetSymbolAddress((void**)&v, g_v);
    cudaGetSymbolAddress((void**)&o, g_o);
    cudaGetSymbolAddress((void**)&xp, g_xp);
    cudaGetSymbolAddress((void**)&wqp, g_wqp);
    cudaGetSymbolAddress((void**)&wkp, g_wkp);
    cudaGetSymbolAddress((void**)&wvp, g_wvp);
    cudaGetSymbolAddress((void**)&wop, g_wop);
    cudaGetSymbolAddress((void**)&op, g_op);

    cudaFuncSetAttribute(rebased_attn_mma,
                         cudaFuncAttributeMaxDynamicSharedMemorySize, ATTN_SMEM7);
    cudaFuncSetAttribute(rebased_attn_mma,
                         cudaFuncAttributePreferredSharedMemoryCarveout, 100);
    cudaFuncSetAttribute(mma_gemm_p,
                         cudaFuncAttributeMaxDynamicSharedMemorySize, GEMM_DSMEM);

    dim3 b256(256);
    const int NGRP = TSEQ * CH / 8;

    // pre-round + K-group permute: X, Wq, Wk, Wv, Wo
    round_permute5<<<dim3(NGRP / 256, 5), b256>>>(
        X, Wq, Wk, Wv, Wo, xp, wqp, wkp, wvp, wop, 5);

    // fused Q/K/V projections (v output tf32-rounded in epilogue)
    mma_gemm_p<<<dim3(16, 16, 3), b256, GEMM_DSMEM>>>(
        xp, wqp, wkp, wvp, q, k, v, 2);

    // feature map (q scaled by D^-0.5, k unscaled; rounded + permuted out)
    featmap<<<dim3(TSEQ * NH / 8, 2), b256>>>(gamma, beta);

    // causal quadratic attention (2 CTAs/SM, q32 x k64 tiles)
    rebased_attn_mma<<<dim3(TSEQ / 32, NH), b256, ATTN_SMEM7>>>();

    // round+permute attention output, then O projection
    round_permute5<<<dim3(NGRP / 256, 1), b256>>>(
        o, o, o, o, o, op, op, op, op, op, 1);
    mma_gemm_p<<<dim3(16, 16, 1), b256, GEMM_DSMEM>>>(
        op, wop, wop, wop, out, out, out, -1);
}

// round 15
// speedup vs baseline: 1.4798x; 1.2150x over previous
#include <cuda_runtime.h>
#include <cstdint>

#define TSEQ 2048
#define CH   2048
#define NH   16
#define HD   128

// Scratch (allocation-free rule: __device__ globals)
__device__ float g_q[TSEQ * CH];
__device__ float g_k[TSEQ * CH];
__device__ float g_v[TSEQ * CH];
// tf32-rounded, K-group-permuted operands
__device__ float g_xp[TSEQ * CH];
__device__ float g_wqp[CH * CH];
__device__ float g_wkp[CH * CH];
__device__ float g_wvp[CH * CH];
__device__ float g_wop[CH * CH];
__device__ float g_op[TSEQ * CH];

// ===========================================================================
// helpers
// ===========================================================================
__device__ __forceinline__ uint32_t smem_to_u32(const void* p) {
    uint32_t a;
    asm("{ .reg .u64 t; cvta.to.shared.u64 t, %1; cvt.u32.u64 %0, t; }"
        : "=r"(a) : "l"(p));
    return a;
}

__device__ __forceinline__ void cp_async16(uint32_t dst, const void* src) {
    asm volatile("cp.async.cg.shared.global [%0], [%1], 16;"
                 :: "r"(dst), "l"(src) : "memory");
}
#define CP_COMMIT() asm volatile("cp.async.commit_group;" ::: "memory")
#define CP_WAIT0()  asm volatile("cp.async.wait_group 0;" ::: "memory")

__device__ __forceinline__ uint32_t f2tf32(float x) {
    uint32_t r;
    asm("cvt.rna.tf32.f32 %0, %1;" : "=r"(r) : "f"(x));
    return r;
}
__device__ __forceinline__ float tf32r(float x) {
    return __uint_as_float(f2tf32(x));
}

// D = A @ B + C, m16n8k8 tf32, row.col
__device__ __forceinline__ void mma_tf32(float* d, const uint32_t* a,
                                         const uint32_t* b, const float* c) {
    asm volatile(
        "mma.sync.aligned.m16n8k8.row.col.f32.tf32.tf32.f32 "
        "{%0,%1,%2,%3}, {%4,%5,%6,%7}, {%8,%9}, {%10,%11,%12,%13};"
        : "=f"(d[0]), "=f"(d[1]), "=f"(d[2]), "=f"(d[3])
        : "r"(a[0]), "r"(a[1]), "r"(a[2]), "r"(a[3]),
          "r"(b[0]), "r"(b[1]),
          "f"(c[0]), "f"(c[1]), "f"(c[2]), "f"(c[3]));
}

// ===========================================================================
// round-to-tf32 + permute each 8-col K-group to [0,4,1,5,2,6,3,7]
// ===========================================================================
__global__ __launch_bounds__(256) void round_permute5(
    const float* __restrict__ s0, const float* __restrict__ s1,
    const float* __restrict__ s2, const float* __restrict__ s3,
    const float* __restrict__ s4,
    float* __restrict__ d0, float* __restrict__ d1, float* __restrict__ d2,
    float* __restrict__ d3, float* __restrict__ d4, int nmat) {
    const int i = blockIdx.x * blockDim.x + threadIdx.x;
    const int m = blockIdx.y;
    if (m >= nmat) return;
    const float* s = (m == 0) ? s0 : (m == 1) ? s1 : (m == 2) ? s2
                   : (m == 3) ? s3 : s4;
    float* d = (m == 0) ? d0 : (m == 1) ? d1 : (m == 2) ? d2
             : (m == 3) ? d3 : d4;
    float4 a = *(const float4*)(s + (size_t)i * 8);
    float4 b = *(const float4*)(s + (size_t)i * 8 + 4);
    float4 o0 = make_float4(tf32r(a.x), tf32r(b.x), tf32r(a.y), tf32r(b.y));
    float4 o1 = make_float4(tf32r(a.z), tf32r(b.z), tf32r(a.w), tf32r(b.w));
    *(float4*)(d + (size_t)i * 8)     = o0;
    *(float4*)(d + (size_t)i * 8 + 4) = o1;
}

// ===========================================================================
// C[M,N] = A[M,K] @ B[N,K]^T  (2048^3) via tf32 mma.sync (verified R7)
// roundz: blockIdx.z whose output is tf32-rounded at store (-1 = none)
// ===========================================================================
#define BK    16
#define LDS_P 24
#define P2    12
#define NTIL  (CH / BK)
#define GEMM_DSMEM (2 * 128 * LDS_P * 4 * 2)

__global__ __launch_bounds__(256, 2) void mma_gemm_p(
    const float* __restrict__ A,
    const float* __restrict__ B0, const float* __restrict__ B1,
    const float* __restrict__ B2,
    float* __restrict__ C0, float* __restrict__ C1, float* __restrict__ C2,
    int roundz) {
    extern __shared__ __align__(16) float gsm[];
    float* As = gsm;
    float* Bs = gsm + 2 * 128 * LDS_P;

    const float* B = (blockIdx.z == 0) ? B0 : (blockIdx.z == 1) ? B1 : B2;
    float*       C = (blockIdx.z == 0) ? C0 : (blockIdx.z == 1) ? C1 : C2;
    const bool rnd = ((int)blockIdx.z == roundz);

    const int tid  = threadIdx.x;
    const int lane = tid & 31;
    const int wid  = tid >> 5;
    const int wm   = (wid & 1) * 64;
    const int wn   = (wid >> 1) * 32;

    const int m0 = blockIdx.y * 128;
    const int n0 = blockIdx.x * 128;
    const float* Ab = A + (size_t)m0 * CH;
    const float* Bb = B + (size_t)n0 * CH;

    const uint32_t sA0 = smem_to_u32(As);
    const uint32_t sB0 = smem_to_u32(Bs);

    const int r0c = tid >> 2;
    const int c4  = (tid & 3) << 2;

    float acc[4][4][4];
#pragma unroll
    for (int mt = 0; mt < 4; mt++)
#pragma unroll
        for (int nt = 0; nt < 4; nt++)
#pragma unroll
            for (int e = 0; e < 4; e++) acc[mt][nt][e] = 0.f;

#pragma unroll
    for (int i = 0; i < 2; i++) {
        int row = r0c + i * 64;
        uint32_t off = (uint32_t)(row * LDS_P + c4) * 4u;
        cp_async16(sA0 + off, Ab + (size_t)row * CH + c4);
        cp_async16(sB0 + off, Bb + (size_t)row * CH + c4);
    }
    CP_COMMIT();

    for (int kt = 0; kt < NTIL; kt++) {
        CP_WAIT0();
        __syncthreads();

        if (kt + 1 < NTIL) {
            const int nbuf = (kt + 1) & 1;
            const int kc   = (kt + 1) * BK;
            const uint32_t sAd = sA0 + (uint32_t)(nbuf * 128 * LDS_P * 4);
            const uint32_t sBd = sB0 + (uint32_t)(nbuf * 128 * LDS_P * 4);
#pragma unroll
            for (int i = 0; i < 2; i++) {
                int row = r0c + i * 64;
                uint32_t off = (uint32_t)(row * LDS_P + c4) * 4u;
                cp_async16(sAd + off, Ab + (size_t)row * CH + kc + c4);
                cp_async16(sBd + off, Bb + (size_t)row * CH + kc + c4);
            }
            CP_COMMIT();
        }

        const int buf = kt & 1;
        const float2* Asb = (const float2*)(As + buf * 128 * LDS_P);
        const float2* Bsb = (const float2*)(Bs + buf * 128 * LDS_P);
#pragma unroll
        for (int ks = 0; ks < 2; ks++) {
            const int jq = ks * 4 + (lane & 3);
            uint32_t af[4][4], bf[4][2];
#pragma unroll
            for (int mt = 0; mt < 4; mt++) {
                int r = wm + mt * 16 + (lane >> 2);
                float2 f0 = Asb[r * P2 + jq];
                float2 f1 = Asb[(r + 8) * P2 + jq];
                af[mt][0] = __float_as_uint(f0.x);
                af[mt][1] = __float_as_uint(f1.x);
                af[mt][2] = __float_as_uint(f0.y);
                af[mt][3] = __float_as_uint(f1.y);
            }
#pragma unroll
            for (int nt = 0; nt < 4; nt++) {
                int cidx = wn + nt * 8 + (lane >> 2);
                float2 f = Bsb[cidx * P2 + jq];
                bf[nt][0] = __float_as_uint(f.x);
                bf[nt][1] = __float_as_uint(f.y);
            }
#pragma unroll
            for (int mt = 0; mt < 4; mt++)
#pragma unroll
                for (int nt = 0; nt < 4; nt++)
                    mma_tf32(acc[mt][nt], af[mt], bf[nt], acc[mt][nt]);
        }
        __syncthreads();
    }

#pragma unroll
    for (int mt = 0; mt < 4; mt++) {
        int r = m0 + wm + mt * 16 + (lane >> 2);
#pragma unroll
        for (int nt = 0; nt < 4; nt++) {
            int cidx = n0 + wn + nt * 8 + 2 * (lane & 3);
            float v0 = acc[mt][nt][0], v1 = acc[mt][nt][1];
            float v2 = acc[mt][nt][2], v3 = acc[mt][nt][3];
            if (rnd) { v0 = tf32r(v0); v1 = tf32r(v1);
                       v2 = tf32r(v2); v3 = tf32r(v3); }
            *(float2*)(C + (size_t)r * CH + cidx)       = make_float2(v0, v1);
            *(float2*)(C + (size_t)(r + 8) * CH + cidx) = make_float2(v2, v3);
        }
    }
}

// ---------------------------------------------------------------------------
// ReBased feature map; output tf32-rounded AND k-group-permuted
// [0,4,1,5,2,6,3,7] (validated: rel_err identical to fp32-store path).
// ---------------------------------------------------------------------------
__global__ __launch_bounds__(256) void featmap(const float* __restrict__ gamma,
                                               const float* __restrict__ beta) {
    const int warp = threadIdx.x >> 5;
    const int lane = threadIdx.x & 31;
    const int row  = blockIdx.x * 8 + warp;
    float* base = (blockIdx.y == 0) ? g_q : g_k;
    const float scale = (blockIdx.y == 0) ? 0.08838834764831845f : 1.0f;
    const int t = row >> 4;
    const int h = row & 15;
    float* p = base + (size_t)t * CH + h * HD;

    float x[4];
    float s = 0.f, sq = 0.f;
#pragma unroll
    for (int r = 0; r < 4; r++) {
        int d = lane + 32 * r;
        float y = p[d] * gamma[d] + beta[d];
        x[r] = y;
        s  += y;
        sq += y * y;
    }
#pragma unroll
    for (int o = 16; o; o >>= 1) {
        s  += __shfl_xor_sync(0xFFFFFFFFu, s, o);   // also orders reads < writes
        sq += __shfl_xor_sync(0xFFFFFFFFu, sq, o);
    }
    const float mu  = s * (1.0f / HD);
    const float var = sq * (1.0f / HD) - mu * mu;
    const float rs  = rsqrtf(var + 1e-5f) * scale;
#pragma unroll
    for (int r = 0; r < 4; r++) {
        int d = lane + 32 * r;
        int pos = (d & ~7) | ((d & 3) << 1) | ((d >> 2) & 1);
        p[pos] = tf32r((x[r] - mu) * rs);
    }
}

// ===========================================================================
// Causal quadratic attention v8 — R14 frame (2 CTAs/SM, q32 x k64 tiles)
// with the shared-atomic z REPLACED by a ones-column mma (zacc in regs:
// rowsum of the SAME tf32-rounded s2 values, no ATOMS, no zsh), and the
// o round+permute FUSED into the epilogue (writes g_op directly).
// QK warp tile 32x8 (wnQ = wid*8); SV warp tile 32x16 (wnO = wid*16).
// smem: qs[32][136] | ks[64][136] | vs[64][136] | s2m[32][72] = 96,256 B
// ===========================================================================
#define QP 136   // q/k/v float pitch (68 float2)
#define VP 72    // s2m float pitch (36 float2)
#define ATTN_SMEM8 ((32*QP + 64*QP + 64*QP + 32*VP) * 4)

__global__ __launch_bounds__(256, 2) void rebased_attn_mma() {
    extern __shared__ __align__(16) float asm_[];
    float* qs  = asm_;                      // [32][QP]
    float* ks  = qs + 32 * QP;              // [64][QP]
    float* vs  = ks + 64 * QP;              // [64][QP]  (k-major, raw d order)
    float* s2m = vs + 64 * QP;              // [32][VP]

    const int tid  = threadIdx.x;
    const int lane = tid & 31;
    const int wid  = tid >> 5;
    const int qt   = 63 - blockIdx.x;       // heavy q32-tiles first
    const int h    = blockIdx.y;
    const int q0   = qt * 32;
    const int nk   = (qt >> 1) + 1;         // number of 64-row k-tiles

    const int wnQ = wid * 8;                // QK 32x8
    const int wnO = wid * 16;               // SV 32x16

    const uint32_t qs_u = smem_to_u32(qs);
    const uint32_t ks_u = smem_to_u32(ks);
    const uint32_t vs_u = smem_to_u32(vs);

    // ---- prologue: cp.async q tile (32x128 = 1024 chunks, 4/thread) ----
#pragma unroll
    for (int i = 0; i < 4; i++) {
        const int idx = tid + i * 256;
        const int r = idx >> 5, c = idx & 31;
        cp_async16(qs_u + (uint32_t)(r * QP + c * 4) * 4u,
                   g_q + (size_t)(q0 + r) * CH + h * HD + c * 4);
    }
    CP_COMMIT();

    float oacc[2][2][4];
    float zacc[2][4];
#pragma unroll
    for (int mt = 0; mt < 2; mt++) {
#pragma unroll
        for (int nt = 0; nt < 2; nt++)
#pragma unroll
            for (int e = 0; e < 4; e++) oacc[mt][nt][e] = 0.f;
#pragma unroll
        for (int e = 0; e < 4; e++) zacc[mt][e] = 0.f;
    }
    const uint32_t ones[2] = {0x3f800000u, 0x3f800000u};

    const int j  = lane & 3;
    const int p0 = (j < 2) ? 4 * j : 4 * j - 7;
    const int p1 = (j < 2) ? 4 * j + 2 : 4 * j - 5;

    for (int kt = 0; kt < nk; kt++) {
        const int k0 = kt * 64;

        // ---- load k/v tile (ks/vs free: barrier at end of prev iter) ----
#pragma unroll
        for (int i = 0; i < 8; i++) {
            const int idx = tid + i * 256;
            const int r = idx >> 5, c = idx & 31;
            const uint32_t so = (uint32_t)(r * QP + c * 4) * 4u;
            cp_async16(ks_u + so, g_k + (size_t)(k0 + r) * CH + h * HD + c * 4);
            cp_async16(vs_u + so, g_v + (size_t)(k0 + r) * CH + h * HD + c * 4);
        }
        CP_COMMIT();
        CP_WAIT0();
        __syncthreads();   // q (iter 0), ks, vs ready; s2m free

        // ---- QK: S = q.k^T (1-pass tf32, LDS.64 only), square+mask,
        //      store tf32-rounded permuted s2 (z via SV ones-mma) ----
        {
            const float2* qf = (const float2*)qs;        // pitch 68
            const float2* kf = (const float2*)ks;        // pitch 68
            float sacc[2][4];
#pragma unroll
            for (int mt = 0; mt < 2; mt++)
#pragma unroll
                for (int e = 0; e < 4; e++) sacc[mt][e] = 0.f;

#pragma unroll 4
            for (int k8 = 0; k8 < 16; k8++) {
                const int fo = k8 * 4 + (lane & 3);
                uint32_t bf[2];
                {
                    const int n = wnQ + (lane >> 2);
                    float2 f = kf[n * (QP / 2) + fo];
                    bf[0] = __float_as_uint(f.x);
                    bf[1] = __float_as_uint(f.y);
                }
#pragma unroll
                for (int mt = 0; mt < 2; mt++) {
                    const int r = mt * 16 + (lane >> 2);
                    float2 f0 = qf[r * (QP / 2) + fo];
                    float2 f1 = qf[(r + 8) * (QP / 2) + fo];
                    uint32_t af[4] = {__float_as_uint(f0.x), __float_as_uint(f1.x),
                                      __float_as_uint(f0.y), __float_as_uint(f1.y)};
                    mma_tf32(sacc[mt], af, bf, sacc[mt]);
                }
            }

            const bool diag = (kt == nk - 1);
            const int  off  = k0 - q0;        // col+off > row ⇒ masked
#pragma unroll
            for (int mt = 0; mt < 2; mt++) {
                const int r0l = mt * 16 + (lane >> 2);
                const int c0l = wnQ + 2 * j;
                float s0 = sacc[mt][0]; s0 *= s0;
                float s1 = sacc[mt][1]; s1 *= s1;
                float s2 = sacc[mt][2]; s2 *= s2;
                float s3 = sacc[mt][3]; s3 *= s3;
                if (diag) {
                    if (c0l + off > r0l)         s0 = 0.f;
                    if (c0l + 1 + off > r0l)     s1 = 0.f;
                    if (c0l + off > r0l + 8)     s2 = 0.f;
                    if (c0l + 1 + off > r0l + 8) s3 = 0.f;
                }
                s2m[r0l * VP + wnQ + p0]       = tf32r(s0);
                s2m[r0l * VP + wnQ + p1]       = tf32r(s1);
                s2m[(r0l + 8) * VP + wnQ + p0] = tf32r(s2);
                s2m[(r0l + 8) * VP + wnQ + p1] = tf32r(s3);
            }
        }
        __syncthreads();   // s2m visible

        // ---- SV: O += S2 @ V; z += S2 @ ones (same rounded values) ----
        {
            const float2* sf = (const float2*)s2m;       // pitch 36
#pragma unroll 2
            for (int k8 = 0; k8 < 8; k8++) {
                const int fo = k8 * 4 + (lane & 3);
                const int kq = k8 * 8 + (lane & 3);
                uint32_t a[2][4];
#pragma unroll
                for (int mt = 0; mt < 2; mt++) {
                    const int r = mt * 16 + (lane >> 2);
                    float2 f0 = sf[r * (VP / 2) + fo];
                    float2 f1 = sf[(r + 8) * (VP / 2) + fo];
                    a[mt][0] = __float_as_uint(f0.x);
                    a[mt][1] = __float_as_uint(f1.x);
                    a[mt][2] = __float_as_uint(f0.y);
                    a[mt][3] = __float_as_uint(f1.y);
                }
#pragma unroll
                for (int nt = 0; nt < 2; nt++) {
                    const int n = wnO + nt * 8 + (lane >> 2);
                    uint32_t b[2];
                    b[0] = __float_as_uint(vs[kq * QP + n]);
                    b[1] = __float_as_uint(vs[(kq + 4) * QP + n]);
#pragma unroll
                    for (int mt = 0; mt < 2; mt++)
                        mma_tf32(oacc[mt][nt], a[mt], b, oacc[mt][nt]);
                }
#pragma unroll
                for (int mt = 0; mt < 2; mt++)
                    mma_tf32(zacc[mt], a[mt], ones, zacc[mt]);
            }
        }
        __syncthreads();   // SV done: ks/vs/s2m reusable next iter
    }

    // ---- epilogue: divide by (z + eps); store rounded + permuted to g_op ----
#pragma unroll
    for (int mt = 0; mt < 2; mt++) {
        const int rl = mt * 16 + (lane >> 2);
        const float inv0 = 1.0f / (zacc[mt][0] + 1e-5f);   // row rl
        const float inv1 = 1.0f / (zacc[mt][2] + 1e-5f);   // row rl + 8
        float* o0 = g_op + (size_t)(q0 + rl) * CH + h * HD;
        float* o1 = g_op + (size_t)(q0 + rl + 8) * CH + h * HD;
#pragma unroll
        for (int nt = 0; nt < 2; nt++) {
            const int gb = wnO + nt * 8;     // 8-group base
            o0[gb + p0] = tf32r(oacc[mt][nt][0] * inv0);
            o0[gb + p1] = tf32r(oacc[mt][nt][1] * inv0);
            o1[gb + p0] = tf32r(oacc[mt][nt][2] * inv1);
            o1[gb + p1] = tf32r(oacc[mt][nt][3] * inv1);
        }
    }
}

// ---------------------------------------------------------------------------
extern "C" void kernel_launch(void* const* d_in, const int* in_sizes, int n_in,
                              void* d_out, int out_size) {
    const float* X     = (const float*)d_in[0];
    const float* Wq    = (const float*)d_in[1];
    const float* Wk    = (const float*)d_in[2];
    const float* Wv    = (const float*)d_in[3];
    const float* Wo    = (const float*)d_in[4];
    const float* gamma = (const float*)d_in[5];
    const float* beta  = (const float*)d_in[6];
    float* out = (float*)d_out;

    float *q, *k, *v, *xp, *wqp, *wkp, *wvp, *wop, *op;
    cudaGetSymbolAddress((void**)&q, g_q);
    cudaGetSymbolAddress((void**)&k, g_k);
    cudaGetSymbolAddress((void**)&v, g_v);
    cudaGetSymbolAddress((void**)&xp, g_xp);
    cudaGetSymbolAddress((void**)&wqp, g_wqp);
    cudaGetSymbolAddress((void**)&wkp, g_wkp);
    cudaGetSymbolAddress((void**)&wvp, g_wvp);
    cudaGetSymbolAddress((void**)&wop, g_wop);
    cudaGetSymbolAddress((void**)&op, g_op);

    cudaFuncSetAttribute(rebased_attn_mma,
                         cudaFuncAttributeMaxDynamicSharedMemorySize, ATTN_SMEM8);
    cudaFuncSetAttribute(rebased_attn_mma,
                         cudaFuncAttributePreferredSharedMemoryCarveout, 100);
    cudaFuncSetAttribute(mma_gemm_p,
                         cudaFuncAttributeMaxDynamicSharedMemorySize, GEMM_DSMEM);

    dim3 b256(256);
    const int NGRP = TSEQ * CH / 8;

    // pre-round + K-group permute: X, Wq, Wk, Wv, Wo
    round_permute5<<<dim3(NGRP / 256, 5), b256>>>(
        X, Wq, Wk, Wv, Wo, xp, wqp, wkp, wvp, wop, 5);

    // fused Q/K/V projections (v output tf32-rounded in epilogue)
    mma_gemm_p<<<dim3(16, 16, 3), b256, GEMM_DSMEM>>>(
        xp, wqp, wkp, wvp, q, k, v, 2);

    // feature map (q scaled by D^-0.5, k unscaled; rounded + permuted out)
    featmap<<<dim3(TSEQ * NH / 8, 2), b256>>>(gamma, beta);

    // causal quadratic attention (no atomics; fused round+permute epilogue)
    rebased_attn_mma<<<dim3(TSEQ / 32, NH), b256, ATTN_SMEM8>>>();

    // O projection (reads g_op written directly by the attention epilogue)
    mma_gemm_p<<<dim3(16, 16, 1), b256, GEMM_DSMEM>>>(
        op, wop, wop, wop, out, out, out, -1);
}

// round 16
// speedup vs baseline: 1.4911x; 1.0076x over previous
#include <cuda_runtime.h>
#include <cstdint>

#define TSEQ 2048
#define CH   2048
#define NH   16
#define HD   128

// Scratch (allocation-free rule: __device__ globals)
__device__ float g_q[TSEQ * CH];
__device__ float g_k[TSEQ * CH];
__device__ float g_v[TSEQ * CH];
// tf32-rounded, K-group-permuted operands
__device__ float g_xp[TSEQ * CH];
__device__ float g_wqp[CH * CH];
__device__ float g_wkp[CH * CH];
__device__ float g_wvp[CH * CH];
__device__ float g_wop[CH * CH];
__device__ float g_op[TSEQ * CH];

// ===========================================================================
// helpers
// ===========================================================================
__device__ __forceinline__ uint32_t smem_to_u32(const void* p) {
    uint32_t a;
    asm("{ .reg .u64 t; cvta.to.shared.u64 t, %1; cvt.u32.u64 %0, t; }"
        : "=r"(a) : "l"(p));
    return a;
}

__device__ __forceinline__ void cp_async16(uint32_t dst, const void* src) {
    asm volatile("cp.async.cg.shared.global [%0], [%1], 16;"
                 :: "r"(dst), "l"(src) : "memory");
}
#define CP_COMMIT() asm volatile("cp.async.commit_group;" ::: "memory")
#define CP_WAIT0()  asm volatile("cp.async.wait_group 0;" ::: "memory")

__device__ __forceinline__ uint32_t f2tf32(float x) {
    uint32_t r;
    asm("cvt.rna.tf32.f32 %0, %1;" : "=r"(r) : "f"(x));
    return r;
}
__device__ __forceinline__ float tf32r(float x) {
    return __uint_as_float(f2tf32(x));
}

// D = A @ B + C, m16n8k8 tf32, row.col
__device__ __forceinline__ void mma_tf32(float* d, const uint32_t* a,
                                         const uint32_t* b, const float* c) {
    asm volatile(
        "mma.sync.aligned.m16n8k8.row.col.f32.tf32.tf32.f32 "
        "{%0,%1,%2,%3}, {%4,%5,%6,%7}, {%8,%9}, {%10,%11,%12,%13};"
        : "=f"(d[0]), "=f"(d[1]), "=f"(d[2]), "=f"(d[3])
        : "r"(a[0]), "r"(a[1]), "r"(a[2]), "r"(a[3]),
          "r"(b[0]), "r"(b[1]),
          "f"(c[0]), "f"(c[1]), "f"(c[2]), "f"(c[3]));
}

// ===========================================================================
// round-to-tf32 + permute each 8-col K-group to [0,4,1,5,2,6,3,7]
// ===========================================================================
__global__ __launch_bounds__(256) void round_permute5(
    const float* __restrict__ s0, const float* __restrict__ s1,
    const float* __restrict__ s2, const float* __restrict__ s3,
    const float* __restrict__ s4,
    float* __restrict__ d0, float* __restrict__ d1, float* __restrict__ d2,
    float* __restrict__ d3, float* __restrict__ d4, int nmat) {
    const int i = blockIdx.x * blockDim.x + threadIdx.x;
    const int m = blockIdx.y;
    if (m >= nmat) return;
    const float* s = (m == 0) ? s0 : (m == 1) ? s1 : (m == 2) ? s2
                   : (m == 3) ? s3 : s4;
    float* d = (m == 0) ? d0 : (m == 1) ? d1 : (m == 2) ? d2
             : (m == 3) ? d3 : d4;
    float4 a = *(const float4*)(s + (size_t)i * 8);
    float4 b = *(const float4*)(s + (size_t)i * 8 + 4);
    float4 o0 = make_float4(tf32r(a.x), tf32r(b.x), tf32r(a.y), tf32r(b.y));
    float4 o1 = make_float4(tf32r(a.z), tf32r(b.z), tf32r(a.w), tf32r(b.w));
    *(float4*)(d + (size_t)i * 8)     = o0;
    *(float4*)(d + (size_t)i * 8 + 4) = o1;
}

// ===========================================================================
// C[M,N] = A[M,K] @ B[N,K]^T  (2048^3) via tf32 mma.sync.
// v9: ONE barrier per k-tile — the top sync of iter kt already proves all
// warps finished compute(kt-1), the only readers of the buffer prefetch(kt+1)
// overwrites. (Numerics identical to R7-verified version.)
// roundz: blockIdx.z whose output is tf32-rounded at store (-1 = none)
// ===========================================================================
#define BK    16
#define LDS_P 24
#define P2    12
#define NTIL  (CH / BK)
#define GEMM_DSMEM (2 * 128 * LDS_P * 4 * 2)

__global__ __launch_bounds__(256, 2) void mma_gemm_p(
    const float* __restrict__ A,
    const float* __restrict__ B0, const float* __restrict__ B1,
    const float* __restrict__ B2,
    float* __restrict__ C0, float* __restrict__ C1, float* __restrict__ C2,
    int roundz) {
    extern __shared__ __align__(16) float gsm[];
    float* As = gsm;
    float* Bs = gsm + 2 * 128 * LDS_P;

    const float* B = (blockIdx.z == 0) ? B0 : (blockIdx.z == 1) ? B1 : B2;
    float*       C = (blockIdx.z == 0) ? C0 : (blockIdx.z == 1) ? C1 : C2;
    const bool rnd = ((int)blockIdx.z == roundz);

    const int tid  = threadIdx.x;
    const int lane = tid & 31;
    const int wid  = tid >> 5;
    const int wm   = (wid & 1) * 64;
    const int wn   = (wid >> 1) * 32;

    const int m0 = blockIdx.y * 128;
    const int n0 = blockIdx.x * 128;
    const float* Ab = A + (size_t)m0 * CH;
    const float* Bb = B + (size_t)n0 * CH;

    const uint32_t sA0 = smem_to_u32(As);
    const uint32_t sB0 = smem_to_u32(Bs);

    const int r0c = tid >> 2;
    const int c4  = (tid & 3) << 2;

    float acc[4][4][4];
#pragma unroll
    for (int mt = 0; mt < 4; mt++)
#pragma unroll
        for (int nt = 0; nt < 4; nt++)
#pragma unroll
            for (int e = 0; e < 4; e++) acc[mt][nt][e] = 0.f;

#pragma unroll
    for (int i = 0; i < 2; i++) {
        int row = r0c + i * 64;
        uint32_t off = (uint32_t)(row * LDS_P + c4) * 4u;
        cp_async16(sA0 + off, Ab + (size_t)row * CH + c4);
        cp_async16(sB0 + off, Bb + (size_t)row * CH + c4);
    }
    CP_COMMIT();

    for (int kt = 0; kt < NTIL; kt++) {
        CP_WAIT0();
        __syncthreads();   // tile kt landed for ALL threads; compute(kt-1) done

        if (kt + 1 < NTIL) {
            const int nbuf = (kt + 1) & 1;
            const int kc   = (kt + 1) * BK;
            const uint32_t sAd = sA0 + (uint32_t)(nbuf * 128 * LDS_P * 4);
            const uint32_t sBd = sB0 + (uint32_t)(nbuf * 128 * LDS_P * 4);
#pragma unroll
            for (int i = 0; i < 2; i++) {
                int row = r0c + i * 64;
                uint32_t off = (uint32_t)(row * LDS_P + c4) * 4u;
                cp_async16(sAd + off, Ab + (size_t)row * CH + kc + c4);
                cp_async16(sBd + off, Bb + (size_t)row * CH + kc + c4);
            }
            CP_COMMIT();
        }

        const int buf = kt & 1;
        const float2* Asb = (const float2*)(As + buf * 128 * LDS_P);
        const float2* Bsb = (const float2*)(Bs + buf * 128 * LDS_P);
#pragma unroll
        for (int ks = 0; ks < 2; ks++) {
            const int jq = ks * 4 + (lane & 3);
            uint32_t af[4][4], bf[4][2];
#pragma unroll
            for (int mt = 0; mt < 4; mt++) {
                int r = wm + mt * 16 + (lane >> 2);
                float2 f0 = Asb[r * P2 + jq];
                float2 f1 = Asb[(r + 8) * P2 + jq];
                af[mt][0] = __float_as_uint(f0.x);
                af[mt][1] = __float_as_uint(f1.x);
                af[mt][2] = __float_as_uint(f0.y);
                af[mt][3] = __float_as_uint(f1.y);
            }
#pragma unroll
            for (int nt = 0; nt < 4; nt++) {
                int cidx = wn + nt * 8 + (lane >> 2);
                float2 f = Bsb[cidx * P2 + jq];
                bf[nt][0] = __float_as_uint(f.x);
                bf[nt][1] = __float_as_uint(f.y);
            }
#pragma unroll
            for (int mt = 0; mt < 4; mt++)
#pragma unroll
                for (int nt = 0; nt < 4; nt++)
                    mma_tf32(acc[mt][nt], af[mt], bf[nt], acc[mt][nt]);
        }
        // no bottom barrier: top sync of kt+1 provides the reuse guarantee
    }

#pragma unroll
    for (int mt = 0; mt < 4; mt++) {
        int r = m0 + wm + mt * 16 + (lane >> 2);
#pragma unroll
        for (int nt = 0; nt < 4; nt++) {
            int cidx = n0 + wn + nt * 8 + 2 * (lane & 3);
            float v0 = acc[mt][nt][0], v1 = acc[mt][nt][1];
            float v2 = acc[mt][nt][2], v3 = acc[mt][nt][3];
            if (rnd) { v0 = tf32r(v0); v1 = tf32r(v1);
                       v2 = tf32r(v2); v3 = tf32r(v3); }
            *(float2*)(C + (size_t)r * CH + cidx)       = make_float2(v0, v1);
            *(float2*)(C + (size_t)(r + 8) * CH + cidx) = make_float2(v2, v3);
        }
    }
}

// ---------------------------------------------------------------------------
// ReBased feature map; output tf32-rounded AND k-group-permuted
// [0,4,1,5,2,6,3,7] (validated: rel_err identical to fp32-store path).
// ---------------------------------------------------------------------------
__global__ __launch_bounds__(256) void featmap(const float* __restrict__ gamma,
                                               const float* __restrict__ beta) {
    const int warp = threadIdx.x >> 5;
    const int lane = threadIdx.x & 31;
    const int row  = blockIdx.x * 8 + warp;
    float* base = (blockIdx.y == 0) ? g_q : g_k;
    const float scale = (blockIdx.y == 0) ? 0.08838834764831845f : 1.0f;
    const int t = row >> 4;
    const int h = row & 15;
    float* p = base + (size_t)t * CH + h * HD;

    float x[4];
    float s = 0.f, sq = 0.f;
#pragma unroll
    for (int r = 0; r < 4; r++) {
        int d = lane + 32 * r;
        float y = p[d] * gamma[d] + beta[d];
        x[r] = y;
        s  += y;
        sq += y * y;
    }
#pragma unroll
    for (int o = 16; o; o >>= 1) {
        s  += __shfl_xor_sync(0xFFFFFFFFu, s, o);   // also orders reads < writes
        sq += __shfl_xor_sync(0xFFFFFFFFu, sq, o);
    }
    const float mu  = s * (1.0f / HD);
    const float var = sq * (1.0f / HD) - mu * mu;
    const float rs  = rsqrtf(var + 1e-5f) * scale;
#pragma unroll
    for (int r = 0; r < 4; r++) {
        int d = lane + 32 * r;
        int pos = (d & ~7) | ((d & 3) << 1) | ((d >> 2) & 1);
        p[pos] = tf32r((x[r] - mu) * rs);
    }
}

// ===========================================================================
// Causal quadratic attention v9 — R15 frame (2 CTAs/SM, q32 x k64, ones-mma
// z, fused round+permute epilogue) with the k-load for kt+1 issued right
// after the post-QK barrier: ks is only read by QK, so the cp.async overlaps
// the entire SV phase + barrier instead of being exposed at the top wait.
// smem: qs[32][136] | ks[64][136] | vs[64][136] | s2m[32][72] = 96,256 B
// ===========================================================================
#define QP 136   // q/k/v float pitch (68 float2)
#define VP 72    // s2m float pitch (36 float2)
#define ATTN_SMEM8 ((32*QP + 64*QP + 64*QP + 32*VP) * 4)

__global__ __launch_bounds__(256, 2) void rebased_attn_mma() {
    extern __shared__ __align__(16) float asm_[];
    float* qs  = asm_;                      // [32][QP]
    float* ks  = qs + 32 * QP;              // [64][QP]
    float* vs  = ks + 64 * QP;              // [64][QP]  (k-major, raw d order)
    float* s2m = vs + 64 * QP;              // [32][VP]

    const int tid  = threadIdx.x;
    const int lane = tid & 31;
    const int wid  = tid >> 5;
    const int qt   = 63 - blockIdx.x;       // heavy q32-tiles first
    const int h    = blockIdx.y;
    const int q0   = qt * 32;
    const int nk   = (qt >> 1) + 1;         // number of 64-row k-tiles

    const int wnQ = wid * 8;                // QK 32x8
    const int wnO = wid * 16;               // SV 32x16

    const uint32_t qs_u = smem_to_u32(qs);
    const uint32_t ks_u = smem_to_u32(ks);
    const uint32_t vs_u = smem_to_u32(vs);

    // ---- prologue: cp.async q tile + k tile 0 (one group) ----
#pragma unroll
    for (int i = 0; i < 4; i++) {
        const int idx = tid + i * 256;
        const int r = idx >> 5, c = idx & 31;
        cp_async16(qs_u + (uint32_t)(r * QP + c * 4) * 4u,
                   g_q + (size_t)(q0 + r) * CH + h * HD + c * 4);
    }
#pragma unroll
    for (int i = 0; i < 8; i++) {
        const int idx = tid + i * 256;
        const int r = idx >> 5, c = idx & 31;
        cp_async16(ks_u + (uint32_t)(r * QP + c * 4) * 4u,
                   g_k + (size_t)r * CH + h * HD + c * 4);
    }
    CP_COMMIT();

    float oacc[2][2][4];
    float zacc[2][4];
#pragma unroll
    for (int mt = 0; mt < 2; mt++) {
#pragma unroll
        for (int nt = 0; nt < 2; nt++)
#pragma unroll
            for (int e = 0; e < 4; e++) oacc[mt][nt][e] = 0.f;
#pragma unroll
        for (int e = 0; e < 4; e++) zacc[mt][e] = 0.f;
    }
    const uint32_t ones[2] = {0x3f800000u, 0x3f800000u};

    const int j  = lane & 3;
    const int p0 = (j < 2) ? 4 * j : 4 * j - 7;
    const int p1 = (j < 2) ? 4 * j + 2 : 4 * j - 5;

    for (int kt = 0; kt < nk; kt++) {
        const int k0 = kt * 64;

        // ---- issue v tile (vs free: post-SV barrier of previous iter) ----
#pragma unroll
        for (int i = 0; i < 8; i++) {
            const int idx = tid + i * 256;
            const int r = idx >> 5, c = idx & 31;
            cp_async16(vs_u + (uint32_t)(r * QP + c * 4) * 4u,
                       g_v + (size_t)(k0 + r) * CH + h * HD + c * 4);
        }
        CP_COMMIT();
        CP_WAIT0();        // k(kt) [issued last iter] + v(kt) landed
        __syncthreads();   // ks, vs (and q on iter 0) visible to all; s2m free

        // ---- QK: S = q.k^T (1-pass tf32, LDS.64 only), square+mask,
        //      store tf32-rounded permuted s2 (z via SV ones-mma) ----
        {
            const float2* qf = (const float2*)qs;        // pitch 68
            const float2* kf = (const float2*)ks;        // pitch 68
            float sacc[2][4];
#pragma unroll
            for (int mt = 0; mt < 2; mt++)
#pragma unroll
                for (int e = 0; e < 4; e++) sacc[mt][e] = 0.f;

#pragma unroll 4
            for (int k8 = 0; k8 < 16; k8++) {
                const int fo = k8 * 4 + (lane & 3);
                uint32_t bf[2];
                {
                    const int n = wnQ + (lane >> 2);
                    float2 f = kf[n * (QP / 2) + fo];
                    bf[0] = __float_as_uint(f.x);
                    bf[1] = __float_as_uint(f.y);
                }
#pragma unroll
                for (int mt = 0; mt < 2; mt++) {
                    const int r = mt * 16 + (lane >> 2);
                    float2 f0 = qf[r * (QP / 2) + fo];
                    float2 f1 = qf[(r + 8) * (QP / 2) + fo];
                    uint32_t af[4] = {__float_as_uint(f0.x), __float_as_uint(f1.x),
                                      __float_as_uint(f0.y), __float_as_uint(f1.y)};
                    mma_tf32(sacc[mt], af, bf, sacc[mt]);
                }
            }

            const bool diag = (kt == nk - 1);
            const int  off  = k0 - q0;        // col+off > row ⇒ masked
#pragma unroll
            for (int mt = 0; mt < 2; mt++) {
                const int r0l = mt * 16 + (lane >> 2);
                const int c0l = wnQ + 2 * j;
                float s0 = sacc[mt][0]; s0 *= s0;
                float s1 = sacc[mt][1]; s1 *= s1;
                float s2 = sacc[mt][2]; s2 *= s2;
                float s3 = sacc[mt][3]; s3 *= s3;
                if (diag) {
                    if (c0l + off > r0l)         s0 = 0.f;
                    if (c0l + 1 + off > r0l)     s1 = 0.f;
                    if (c0l + off > r0l + 8)     s2 = 0.f;
                    if (c0l + 1 + off > r0l + 8) s3 = 0.f;
                }
                s2m[r0l * VP + wnQ + p0]       = tf32r(s0);
                s2m[r0l * VP + wnQ + p1]       = tf32r(s1);
                s2m[(r0l + 8) * VP + wnQ + p0] = tf32r(s2);
                s2m[(r0l + 8) * VP + wnQ + p1] = tf32r(s3);
            }
        }
        __syncthreads();   // s2m visible; ALL warps done reading ks

        // ---- issue k tile kt+1 now: overlaps SV + barrier (QK-only buffer)
        if (kt + 1 < nk) {
            const int kn = (kt + 1) * 64;
#pragma unroll
            for (int i = 0; i < 8; i++) {
                const int idx = tid + i * 256;
                const int r = idx >> 5, c = idx & 31;
                cp_async16(ks_u + (uint32_t)(r * QP + c * 4) * 4u,
                           g_k + (size_t)(kn + r) * CH + h * HD + c * 4);
            }
            CP_COMMIT();
        }

        // ---- SV: O += S2 @ V; z += S2 @ ones (same rounded values) ----
        {
            const float2* sf = (const float2*)s2m;       // pitch 36
#pragma unroll 2
            for (int k8 = 0; k8 < 8; k8++) {
                const int fo = k8 * 4 + (lane & 3);
                const int kq = k8 * 8 + (lane & 3);
                uint32_t a[2][4];
#pragma unroll
                for (int mt = 0; mt < 2; mt++) {
                    const int r = mt * 16 + (lane >> 2);
                    float2 f0 = sf[r * (VP / 2) + fo];
                    float2 f1 = sf[(r + 8) * (VP / 2) + fo];
                    a[mt][0] = __float_as_uint(f0.x);
                    a[mt][1] = __float_as_uint(f1.x);
                    a[mt][2] = __float_as_uint(f0.y);
                    a[mt][3] = __float_as_uint(f1.y);
                }
#pragma unroll
                for (int nt = 0; nt < 2; nt++) {
                    const int n = wnO + nt * 8 + (lane >> 2);
                    uint32_t b[2];
                    b[0] = __float_as_uint(vs[kq * QP + n]);
                    b[1] = __float_as_uint(vs[(kq + 4) * QP + n]);
#pragma unroll
                    for (int mt = 0; mt < 2; mt++)
                        mma_tf32(oacc[mt][nt], a[mt], b, oacc[mt][nt]);
                }
#pragma unroll
                for (int mt = 0; mt < 2; mt++)
                    mma_tf32(zacc[mt], a[mt], ones, zacc[mt]);
            }
        }
        __syncthreads();   // SV done: vs/s2m reusable next iter
    }

    // ---- epilogue: divide by (z + eps); store rounded + permuted to g_op ----
#pragma unroll
    for (int mt = 0; mt < 2; mt++) {
        const int rl = mt * 16 + (lane >> 2);
        const float inv0 = 1.0f / (zacc[mt][0] + 1e-5f);   // row rl
        const float inv1 = 1.0f / (zacc[mt][2] + 1e-5f);   // row rl + 8
        float* o0 = g_op + (size_t)(q0 + rl) * CH + h * HD;
        float* o1 = g_op + (size_t)(q0 + rl + 8) * CH + h * HD;
#pragma unroll
        for (int nt = 0; nt < 2; nt++) {
            const int gb = wnO + nt * 8;     // 8-group base
            o0[gb + p0] = tf32r(oacc[mt][nt][0] * inv0);
            o0[gb + p1] = tf32r(oacc[mt][nt][1] * inv0);
            o1[gb + p0] = tf32r(oacc[mt][nt][2] * inv1);
            o1[gb + p1] = tf32r(oacc[mt][nt][3] * inv1);
        }
    }
}

// ---------------------------------------------------------------------------
extern "C" void kernel_launch(void* const* d_in, const int* in_sizes, int n_in,
                              void* d_out, int out_size) {
    const float* X     = (const float*)d_in[0];
    const float* Wq    = (const float*)d_in[1];
    const float* Wk    = (const float*)d_in[2];
    const float* Wv    = (const float*)d_in[3];
    const float* Wo    = (const float*)d_in[4];
    const float* gamma = (const float*)d_in[5];
    const float* beta  = (const float*)d_in[6];
    float* out = (float*)d_out;

    float *q, *k, *v, *xp, *wqp, *wkp, *wvp, *wop, *op;
    cudaGetSymbolAddress((void**)&q, g_q);
    cudaGetSymbolAddress((void**)&k, g_k);
    cudaGetSymbolAddress((void**)&v, g_v);
    cudaGetSymbolAddress((void**)&xp, g_xp);
    cudaGetSymbolAddress((void**)&wqp, g_wqp);
    cudaGetSymbolAddress((void**)&wkp, g_wkp);
    cudaGetSymbolAddress((void**)&wvp, g_wvp);
    cudaGetSymbolAddress((void**)&wop, g_wop);
    cudaGetSymbolAddress((void**)&op, g_op);

    cudaFuncSetAttribute(rebased_attn_mma,
                         cudaFuncAttributeMaxDynamicSharedMemorySize, ATTN_SMEM8);
    cudaFuncSetAttribute(rebased_attn_mma,
                         cudaFuncAttributePreferredSharedMemoryCarveout, 100);
    cudaFuncSetAttribute(mma_gemm_p,
                         cudaFuncAttributeMaxDynamicSharedMemorySize, GEMM_DSMEM);

    dim3 b256(256);
    const int NGRP = TSEQ * CH / 8;

    // pre-round + K-group permute: X, Wq, Wk, Wv, Wo
    round_permute5<<<dim3(NGRP / 256, 5), b256>>>(
        X, Wq, Wk, Wv, Wo, xp, wqp, wkp, wvp, wop, 5);

    // fused Q/K/V projections (v output tf32-rounded in epilogue)
    mma_gemm_p<<<dim3(16, 16, 3), b256, GEMM_DSMEM>>>(
        xp, wqp, wkp, wvp, q, k, v, 2);

    // feature map (q scaled by D^-0.5, k unscaled; rounded + permuted out)
    featmap<<<dim3(TSEQ * NH / 8, 2), b256>>>(gamma, beta);

    // causal quadratic attention (no atomics; k-load overlapped with SV)
    rebased_attn_mma<<<dim3(TSEQ / 32, NH), b256, ATTN_SMEM8>>>();

    // O projection (reads g_op written directly by the attention epilogue)
    mma_gemm_p<<<dim3(16, 16, 1), b256, GEMM_DSMEM>>>(
        op, wop, wop, wop, out, out, out, -1);
}

// round 17
// speedup vs baseline: 1.4987x; 1.0051x over previous
#include <cuda_runtime.h>
#include <cstdint>

#define TSEQ 2048
#define CH   2048
#define NH   16
#define HD   128

// Scratch (allocation-free rule: __device__ globals)
__device__ float g_q[TSEQ * CH];
__device__ float g_k[TSEQ * CH];
__device__ float g_v[TSEQ * CH];
// tf32-rounded, K-group-permuted operands
__device__ float g_xp[TSEQ * CH];
__device__ float g_wqp[CH * CH];
__device__ float g_wkp[CH * CH];
__device__ float g_wvp[CH * CH];
__device__ float g_wop[CH * CH];
__device__ float g_op[TSEQ * CH];

// ===========================================================================
// helpers
// ===========================================================================
__device__ __forceinline__ uint32_t smem_to_u32(const void* p) {
    uint32_t a;
    asm("{ .reg .u64 t; cvta.to.shared.u64 t, %1; cvt.u32.u64 %0, t; }"
        : "=r"(a) : "l"(p));
    return a;
}

__device__ __forceinline__ void cp_async16(uint32_t dst, const void* src) {
    asm volatile("cp.async.cg.shared.global [%0], [%1], 16;"
                 :: "r"(dst), "l"(src) : "memory");
}
#define CP_COMMIT() asm volatile("cp.async.commit_group;" ::: "memory")
#define CP_WAIT0()  asm volatile("cp.async.wait_group 0;" ::: "memory")

__device__ __forceinline__ uint32_t f2tf32(float x) {
    uint32_t r;
    asm("cvt.rna.tf32.f32 %0, %1;" : "=r"(r) : "f"(x));
    return r;
}
__device__ __forceinline__ float tf32r(float x) {
    return __uint_as_float(f2tf32(x));
}

// D = A @ B + C, m16n8k8 tf32, row.col
__device__ __forceinline__ void mma_tf32(float* d, const uint32_t* a,
                                         const uint32_t* b, const float* c) {
    asm volatile(
        "mma.sync.aligned.m16n8k8.row.col.f32.tf32.tf32.f32 "
        "{%0,%1,%2,%3}, {%4,%5,%6,%7}, {%8,%9}, {%10,%11,%12,%13};"
        : "=f"(d[0]), "=f"(d[1]), "=f"(d[2]), "=f"(d[3])
        : "r"(a[0]), "r"(a[1]), "r"(a[2]), "r"(a[3]),
          "r"(b[0]), "r"(b[1]),
          "f"(c[0]), "f"(c[1]), "f"(c[2]), "f"(c[3]));
}

// ===========================================================================
// round-to-tf32 + permute each 8-col K-group to [0,4,1,5,2,6,3,7]
// ===========================================================================
__global__ __launch_bounds__(256) void round_permute5(
    const float* __restrict__ s0, const float* __restrict__ s1,
    const float* __restrict__ s2, const float* __restrict__ s3,
    const float* __restrict__ s4,
    float* __restrict__ d0, float* __restrict__ d1, float* __restrict__ d2,
    float* __restrict__ d3, float* __restrict__ d4, int nmat) {
    const int i = blockIdx.x * blockDim.x + threadIdx.x;
    const int m = blockIdx.y;
    if (m >= nmat) return;
    const float* s = (m == 0) ? s0 : (m == 1) ? s1 : (m == 2) ? s2
                   : (m == 3) ? s3 : s4;
    float* d = (m == 0) ? d0 : (m == 1) ? d1 : (m == 2) ? d2
             : (m == 3) ? d3 : d4;
    float4 a = *(const float4*)(s + (size_t)i * 8);
    float4 b = *(const float4*)(s + (size_t)i * 8 + 4);
    float4 o0 = make_float4(tf32r(a.x), tf32r(b.x), tf32r(a.y), tf32r(b.y));
    float4 o1 = make_float4(tf32r(a.z), tf32r(b.z), tf32r(a.w), tf32r(b.w));
    *(float4*)(d + (size_t)i * 8)     = o0;
    *(float4*)(d + (size_t)i * 8 + 4) = o1;
}

// ===========================================================================
// C[M,N] = A[M,K] @ B[N,K]^T  (2048^3) via tf32 mma.sync.
// ONE barrier per k-tile (verified R16).
// roundz: blockIdx.z whose output is tf32-rounded at store (-1 = none)
// ===========================================================================
#define BK    16
#define LDS_P 24
#define P2    12
#define NTIL  (CH / BK)
#define GEMM_DSMEM (2 * 128 * LDS_P * 4 * 2)

__global__ __launch_bounds__(256, 2) void mma_gemm_p(
    const float* __restrict__ A,
    const float* __restrict__ B0, const float* __restrict__ B1,
    const float* __restrict__ B2,
    float* __restrict__ C0, float* __restrict__ C1, float* __restrict__ C2,
    int roundz) {
    extern __shared__ __align__(16) float gsm[];
    float* As = gsm;
    float* Bs = gsm + 2 * 128 * LDS_P;

    const float* B = (blockIdx.z == 0) ? B0 : (blockIdx.z == 1) ? B1 : B2;
    float*       C = (blockIdx.z == 0) ? C0 : (blockIdx.z == 1) ? C1 : C2;
    const bool rnd = ((int)blockIdx.z == roundz);

    const int tid  = threadIdx.x;
    const int lane = tid & 31;
    const int wid  = tid >> 5;
    const int wm   = (wid & 1) * 64;
    const int wn   = (wid >> 1) * 32;

    const int m0 = blockIdx.y * 128;
    const int n0 = blockIdx.x * 128;
    const float* Ab = A + (size_t)m0 * CH;
    const float* Bb = B + (size_t)n0 * CH;

    const uint32_t sA0 = smem_to_u32(As);
    const uint32_t sB0 = smem_to_u32(Bs);

    const int r0c = tid >> 2;
    const int c4  = (tid & 3) << 2;

    float acc[4][4][4];
#pragma unroll
    for (int mt = 0; mt < 4; mt++)
#pragma unroll
        for (int nt = 0; nt < 4; nt++)
#pragma unroll
            for (int e = 0; e < 4; e++) acc[mt][nt][e] = 0.f;

#pragma unroll
    for (int i = 0; i < 2; i++) {
        int row = r0c + i * 64;
        uint32_t off = (uint32_t)(row * LDS_P + c4) * 4u;
        cp_async16(sA0 + off, Ab + (size_t)row * CH + c4);
        cp_async16(sB0 + off, Bb + (size_t)row * CH + c4);
    }
    CP_COMMIT();

    for (int kt = 0; kt < NTIL; kt++) {
        CP_WAIT0();
        __syncthreads();   // tile kt landed for ALL threads; compute(kt-1) done

        if (kt + 1 < NTIL) {
            const int nbuf = (kt + 1) & 1;
            const int kc   = (kt + 1) * BK;
            const uint32_t sAd = sA0 + (uint32_t)(nbuf * 128 * LDS_P * 4);
            const uint32_t sBd = sB0 + (uint32_t)(nbuf * 128 * LDS_P * 4);
#pragma unroll
            for (int i = 0; i < 2; i++) {
                int row = r0c + i * 64;
                uint32_t off = (uint32_t)(row * LDS_P + c4) * 4u;
                cp_async16(sAd + off, Ab + (size_t)row * CH + kc + c4);
                cp_async16(sBd + off, Bb + (size_t)row * CH + kc + c4);
            }
            CP_COMMIT();
        }

        const int buf = kt & 1;
        const float2* Asb = (const float2*)(As + buf * 128 * LDS_P);
        const float2* Bsb = (const float2*)(Bs + buf * 128 * LDS_P);
#pragma unroll
        for (int ks = 0; ks < 2; ks++) {
            const int jq = ks * 4 + (lane & 3);
            uint32_t af[4][4], bf[4][2];
#pragma unroll
            for (int mt = 0; mt < 4; mt++) {
                int r = wm + mt * 16 + (lane >> 2);
                float2 f0 = Asb[r * P2 + jq];
                float2 f1 = Asb[(r + 8) * P2 + jq];
                af[mt][0] = __float_as_uint(f0.x);
                af[mt][1] = __float_as_uint(f1.x);
                af[mt][2] = __float_as_uint(f0.y);
                af[mt][3] = __float_as_uint(f1.y);
            }
#pragma unroll
            for (int nt = 0; nt < 4; nt++) {
                int cidx = wn + nt * 8 + (lane >> 2);
                float2 f = Bsb[cidx * P2 + jq];
                bf[nt][0] = __float_as_uint(f.x);
                bf[nt][1] = __float_as_uint(f.y);
            }
#pragma unroll
            for (int mt = 0; mt < 4; mt++)
#pragma unroll
                for (int nt = 0; nt < 4; nt++)
                    mma_tf32(acc[mt][nt], af[mt], bf[nt], acc[mt][nt]);
        }
        // no bottom barrier: top sync of kt+1 provides the reuse guarantee
    }

#pragma unroll
    for (int mt = 0; mt < 4; mt++) {
        int r = m0 + wm + mt * 16 + (lane >> 2);
#pragma unroll
        for (int nt = 0; nt < 4; nt++) {
            int cidx = n0 + wn + nt * 8 + 2 * (lane & 3);
            float v0 = acc[mt][nt][0], v1 = acc[mt][nt][1];
            float v2 = acc[mt][nt][2], v3 = acc[mt][nt][3];
            if (rnd) { v0 = tf32r(v0); v1 = tf32r(v1);
                       v2 = tf32r(v2); v3 = tf32r(v3); }
            *(float2*)(C + (size_t)r * CH + cidx)       = make_float2(v0, v1);
            *(float2*)(C + (size_t)(r + 8) * CH + cidx) = make_float2(v2, v3);
        }
    }
}

// ---------------------------------------------------------------------------
// ReBased feature map; output tf32-rounded AND k-group-permuted
// [0,4,1,5,2,6,3,7] (validated: rel_err identical to fp32-store path).
// ---------------------------------------------------------------------------
__global__ __launch_bounds__(256) void featmap(const float* __restrict__ gamma,
                                               const float* __restrict__ beta) {
    const int warp = threadIdx.x >> 5;
    const int lane = threadIdx.x & 31;
    const int row  = blockIdx.x * 8 + warp;
    float* base = (blockIdx.y == 0) ? g_q : g_k;
    const float scale = (blockIdx.y == 0) ? 0.08838834764831845f : 1.0f;
    const int t = row >> 4;
    const int h = row & 15;
    float* p = base + (size_t)t * CH + h * HD;

    float x[4];
    float s = 0.f, sq = 0.f;
#pragma unroll
    for (int r = 0; r < 4; r++) {
        int d = lane + 32 * r;
        float y = p[d] * gamma[d] + beta[d];
        x[r] = y;
        s  += y;
        sq += y * y;
    }
#pragma unroll
    for (int o = 16; o; o >>= 1) {
        s  += __shfl_xor_sync(0xFFFFFFFFu, s, o);   // also orders reads < writes
        sq += __shfl_xor_sync(0xFFFFFFFFu, sq, o);
    }
    const float mu  = s * (1.0f / HD);
    const float var = sq * (1.0f / HD) - mu * mu;
    const float rs  = rsqrtf(var + 1e-5f) * scale;
#pragma unroll
    for (int r = 0; r < 4; r++) {
        int d = lane + 32 * r;
        int pos = (d & ~7) | ((d & 3) << 1) | ((d >> 2) & 1);
        p[pos] = tf32r((x[r] - mu) * rs);
    }
}

// ===========================================================================
// Causal quadratic attention v10 — R16 frame (2 CTAs/SM, q32 x k64, k-load
// overlapped with SV, fused round+permute epilogue), with the ones-column
// z-mma REPLACED by FADD accumulation on the idle fma pipe: in SV, the
// loaded s2 fragments are the exact masked-rounded values; across the 8 k8
// steps each thread covers all columns ≡ (lane&3) mod 4, so z[row] += f.x+f.y
// plus a quad shfl-reduction in the epilogue gives the full rowsum of the
// SAME rounded values (only fp32 add order changes). Frees 16 HMMA/warp/tile
// (20% of attention tensor-pipe work).
// smem: qs[32][136] | ks[64][136] | vs[64][136] | s2m[32][72] = 96,256 B
// ===========================================================================
#define QP 136   // q/k/v float pitch (68 float2)
#define VP 72    // s2m float pitch (36 float2)
#define ATTN_SMEM8 ((32*QP + 64*QP + 64*QP + 32*VP) * 4)

__global__ __launch_bounds__(256, 2) void rebased_attn_mma() {
    extern __shared__ __align__(16) float asm_[];
    float* qs  = asm_;                      // [32][QP]
    float* ks  = qs + 32 * QP;              // [64][QP]
    float* vs  = ks + 64 * QP;              // [64][QP]  (k-major, raw d order)
    float* s2m = vs + 64 * QP;              // [32][VP]

    const int tid  = threadIdx.x;
    const int lane = tid & 31;
    const int wid  = tid >> 5;
    const int qt   = 63 - blockIdx.x;       // heavy q32-tiles first
    const int h    = blockIdx.y;
    const int q0   = qt * 32;
    const int nk   = (qt >> 1) + 1;         // number of 64-row k-tiles

    const int wnQ = wid * 8;                // QK 32x8
    const int wnO = wid * 16;               // SV 32x16

    const uint32_t qs_u = smem_to_u32(qs);
    const uint32_t ks_u = smem_to_u32(ks);
    const uint32_t vs_u = smem_to_u32(vs);

    // ---- prologue: cp.async q tile + k tile 0 (one group) ----
#pragma unroll
    for (int i = 0; i < 4; i++) {
        const int idx = tid + i * 256;
        const int r = idx >> 5, c = idx & 31;
        cp_async16(qs_u + (uint32_t)(r * QP + c * 4) * 4u,
                   g_q + (size_t)(q0 + r) * CH + h * HD + c * 4);
    }
#pragma unroll
    for (int i = 0; i < 8; i++) {
        const int idx = tid + i * 256;
        const int r = idx >> 5, c = idx & 31;
        cp_async16(ks_u + (uint32_t)(r * QP + c * 4) * 4u,
                   g_k + (size_t)r * CH + h * HD + c * 4);
    }
    CP_COMMIT();

    float oacc[2][2][4];
    float zacc[4];                          // rows rl, rl+8, rl+16, rl+24
#pragma unroll
    for (int mt = 0; mt < 2; mt++)
#pragma unroll
        for (int nt = 0; nt < 2; nt++)
#pragma unroll
            for (int e = 0; e < 4; e++) oacc[mt][nt][e] = 0.f;
#pragma unroll
    for (int e = 0; e < 4; e++) zacc[e] = 0.f;

    const int j  = lane & 3;
    const int p0 = (j < 2) ? 4 * j : 4 * j - 7;
    const int p1 = (j < 2) ? 4 * j + 2 : 4 * j - 5;

    for (int kt = 0; kt < nk; kt++) {
        const int k0 = kt * 64;

        // ---- issue v tile (vs free: post-SV barrier of previous iter) ----
#pragma unroll
        for (int i = 0; i < 8; i++) {
            const int idx = tid + i * 256;
            const int r = idx >> 5, c = idx & 31;
            cp_async16(vs_u + (uint32_t)(r * QP + c * 4) * 4u,
                       g_v + (size_t)(k0 + r) * CH + h * HD + c * 4);
        }
        CP_COMMIT();
        CP_WAIT0();        // k(kt) [issued last iter] + v(kt) landed
        __syncthreads();   // ks, vs (and q on iter 0) visible to all; s2m free

        // ---- QK: S = q.k^T (1-pass tf32, LDS.64 only), square+mask,
        //      store tf32-rounded permuted s2 ----
        {
            const float2* qf = (const float2*)qs;        // pitch 68
            const float2* kf = (const float2*)ks;        // pitch 68
            float sacc[2][4];
#pragma unroll
            for (int mt = 0; mt < 2; mt++)
#pragma unroll
                for (int e = 0; e < 4; e++) sacc[mt][e] = 0.f;

#pragma unroll 4
            for (int k8 = 0; k8 < 16; k8++) {
                const int fo = k8 * 4 + (lane & 3);
                uint32_t bf[2];
                {
                    const int n = wnQ + (lane >> 2);
                    float2 f = kf[n * (QP / 2) + fo];
                    bf[0] = __float_as_uint(f.x);
                    bf[1] = __float_as_uint(f.y);
                }
#pragma unroll
                for (int mt = 0; mt < 2; mt++) {
                    const int r = mt * 16 + (lane >> 2);
                    float2 f0 = qf[r * (QP / 2) + fo];
                    float2 f1 = qf[(r + 8) * (QP / 2) + fo];
                    uint32_t af[4] = {__float_as_uint(f0.x), __float_as_uint(f1.x),
                                      __float_as_uint(f0.y), __float_as_uint(f1.y)};
                    mma_tf32(sacc[mt], af, bf, sacc[mt]);
                }
            }

            const bool diag = (kt == nk - 1);
            const int  off  = k0 - q0;        // col+off > row ⇒ masked
#pragma unroll
            for (int mt = 0; mt < 2; mt++) {
                const int r0l = mt * 16 + (lane >> 2);
                const int c0l = wnQ + 2 * j;
                float s0 = sacc[mt][0]; s0 *= s0;
                float s1 = sacc[mt][1]; s1 *= s1;
                float s2 = sacc[mt][2]; s2 *= s2;
                float s3 = sacc[mt][3]; s3 *= s3;
                if (diag) {
                    if (c0l + off > r0l)         s0 = 0.f;
                    if (c0l + 1 + off > r0l)     s1 = 0.f;
                    if (c0l + off > r0l + 8)     s2 = 0.f;
                    if (c0l + 1 + off > r0l + 8) s3 = 0.f;
                }
                s2m[r0l * VP + wnQ + p0]       = tf32r(s0);
                s2m[r0l * VP + wnQ + p1]       = tf32r(s1);
                s2m[(r0l + 8) * VP + wnQ + p0] = tf32r(s2);
                s2m[(r0l + 8) * VP + wnQ + p1] = tf32r(s3);
            }
        }
        __syncthreads();   // s2m visible; ALL warps done reading ks

        // ---- issue k tile kt+1 now: overlaps SV + barrier (QK-only buffer)
        if (kt + 1 < nk) {
            const int kn = (kt + 1) * 64;
#pragma unroll
            for (int i = 0; i < 8; i++) {
                const int idx = tid + i * 256;
                const int r = idx >> 5, c = idx & 31;
                cp_async16(ks_u + (uint32_t)(r * QP + c * 4) * 4u,
                           g_k + (size_t)(kn + r) * CH + h * HD + c * 4);
            }
            CP_COMMIT();
        }

        // ---- SV: O += S2 @ V; z += per-thread FADD rowsums of the SAME
        //      rounded s2 fragment values (quad-reduced in the epilogue) ----
        {
            const float2* sf = (const float2*)s2m;       // pitch 36
#pragma unroll 2
            for (int k8 = 0; k8 < 8; k8++) {
                const int fo = k8 * 4 + (lane & 3);
                const int kq = k8 * 8 + (lane & 3);
                uint32_t a[2][4];
#pragma unroll
                for (int mt = 0; mt < 2; mt++) {
                    const int r = mt * 16 + (lane >> 2);
                    float2 f0 = sf[r * (VP / 2) + fo];
                    float2 f1 = sf[(r + 8) * (VP / 2) + fo];
                    a[mt][0] = __float_as_uint(f0.x);
                    a[mt][1] = __float_as_uint(f1.x);
                    a[mt][2] = __float_as_uint(f0.y);
                    a[mt][3] = __float_as_uint(f1.y);
                    zacc[2 * mt + 0] += f0.x + f0.y;     // row r
                    zacc[2 * mt + 1] += f1.x + f1.y;     // row r + 8
                }
#pragma unroll
                for (int nt = 0; nt < 2; nt++) {
                    const int n = wnO + nt * 8 + (lane >> 2);
                    uint32_t b[2];
                    b[0] = __float_as_uint(vs[kq * QP + n]);
                    b[1] = __float_as_uint(vs[(kq + 4) * QP + n]);
#pragma unroll
                    for (int mt = 0; mt < 2; mt++)
                        mma_tf32(oacc[mt][nt], a[mt], b, oacc[mt][nt]);
                }
            }
        }
        __syncthreads();   // SV done: vs/s2m reusable next iter
    }

    // ---- epilogue: quad-reduce z (lanes j=0..3 hold cols ≡ j mod 4),
    //      divide by (z + eps); store rounded + permuted to g_op ----
#pragma unroll
    for (int e = 0; e < 4; e++) {
        zacc[e] += __shfl_xor_sync(0xFFFFFFFFu, zacc[e], 1);
        zacc[e] += __shfl_xor_sync(0xFFFFFFFFu, zacc[e], 2);
    }
#pragma unroll
    for (int mt = 0; mt < 2; mt++) {
        const int rl = mt * 16 + (lane >> 2);
        const float inv0 = 1.0f / (zacc[2 * mt + 0] + 1e-5f);   // row rl
        const float inv1 = 1.0f / (zacc[2 * mt + 1] + 1e-5f);   // row rl + 8
        float* o0 = g_op + (size_t)(q0 + rl) * CH + h * HD;
        float* o1 = g_op + (size_t)(q0 + rl + 8) * CH + h * HD;
#pragma unroll
        for (int nt = 0; nt < 2; nt++) {
            const int gb = wnO + nt * 8;     // 8-group base
            o0[gb + p0] = tf32r(oacc[mt][nt][0] * inv0);
            o0[gb + p1] = tf32r(oacc[mt][nt][1] * inv0);
            o1[gb + p0] = tf32r(oacc[mt][nt][2] * inv1);
            o1[gb + p1] = tf32r(oacc[mt][nt][3] * inv1);
        }
    }
}

// ---------------------------------------------------------------------------
extern "C" void kernel_launch(void* const* d_in, const int* in_sizes, int n_in,
                              void* d_out, int out_size) {
    const float* X     = (const float*)d_in[0];
    const float* Wq    = (const float*)d_in[1];
    const float* Wk    = (const float*)d_in[2];
    const float* Wv    = (const float*)d_in[3];
    const float* Wo    = (const float*)d_in[4];
    const float* gamma = (const float*)d_in[5];
    const float* beta  = (const float*)d_in[6];
    float* out = (float*)d_out;

    float *q, *k, *v, *xp, *wqp, *wkp, *wvp, *wop, *op;
    cudaGetSymbolAddress((void**)&q, g_q);
    cudaGetSymbolAddress((void**)&k, g_k);
    cudaGetSymbolAddress((void**)&v, g_v);
    cudaGetSymbolAddress((void**)&xp, g_xp);
    cudaGetSymbolAddress((void**)&wqp, g_wqp);
    cudaGetSymbolAddress((void**)&wkp, g_wkp);
    cudaGetSymbolAddress((void**)&wvp, g_wvp);
    cudaGetSymbolAddress((void**)&wop, g_wop);
    cudaGetSymbolAddress((void**)&op, g_op);

    cudaFuncSetAttribute(rebased_attn_mma,
                         cudaFuncAttributeMaxDynamicSharedMemorySize, ATTN_SMEM8);
    cudaFuncSetAttribute(rebased_attn_mma,
                         cudaFuncAttributePreferredSharedMemoryCarveout, 100);
    cudaFuncSetAttribute(mma_gemm_p,
                         cudaFuncAttributeMaxDynamicSharedMemorySize, GEMM_DSMEM);

    dim3 b256(256);
    const int NGRP = TSEQ * CH / 8;

    // pre-round + K-group permute: X, Wq, Wk, Wv, Wo
    round_permute5<<<dim3(NGRP / 256, 5), b256>>>(
        X, Wq, Wk, Wv, Wo, xp, wqp, wkp, wvp, wop, 5);

    // fused Q/K/V projections (v output tf32-rounded in epilogue)
    mma_gemm_p<<<dim3(16, 16, 3), b256, GEMM_DSMEM>>>(
        xp, wqp, wkp, wvp, q, k, v, 2);

    // feature map (q scaled by D^-0.5, k unscaled; rounded + permuted out)
    featmap<<<dim3(TSEQ * NH / 8, 2), b256>>>(gamma, beta);

    // causal quadratic attention (FADD z on fma pipe; no z-mma)
    rebased_attn_mma<<<dim3(TSEQ / 32, NH), b256, ATTN_SMEM8>>>();

    // O projection (reads g_op written directly by the attention epilogue)
    mma_gemm_p<<<dim3(16, 16, 1), b256, GEMM_DSMEM>>>(
        op, wop, wop, wop, out, out, out, -1);
}